// round 1
// baseline (speedup 1.0000x reference)
#include <cuda_runtime.h>
#include <cuda_bf16.h>
#include <math.h>

#define S_LEN 2048
#define HID   4096
#define NH    32
#define NKV   8
#define HD    128
#define KVDIM (NKV * HD)   // 1024

// Scratch (allocations are forbidden; __device__ globals are the sanctioned path)
__device__ float g_q[S_LEN * HID];
__device__ float g_k[S_LEN * KVDIM];
__device__ float g_v[S_LEN * KVDIM];
__device__ float g_attn[S_LEN * HID];

// ---------------------------------------------------------------------------
// GEMM: C[M,N] = A[M,K] @ B[N,K]^T   (torch Linear: y = x @ W.T)
// 128x128 tile, BK=8, 256 threads, 8x8 micro-tile, register prefetch.
// ---------------------------------------------------------------------------
#define BM  128
#define BN  128
#define BKK 8

__global__ __launch_bounds__(256) void gemm_nt(const float* __restrict__ A,
                                               const float* __restrict__ B,
                                               float* __restrict__ C,
                                               int M, int N, int K) {
    __shared__ float As[BKK][BM];
    __shared__ float Bs[BKK][BN];

    const int bm  = blockIdx.y * BM;
    const int bn  = blockIdx.x * BN;
    const int tid = threadIdx.x;
    const int lrow = tid >> 1;          // 0..127
    const int lcol = (tid & 1) * 4;     // 0 or 4
    const int tx = tid & 15;
    const int ty = tid >> 4;

    const float* Ag = A + (size_t)(bm + lrow) * K + lcol;
    const float* Bg = B + (size_t)(bn + lrow) * K + lcol;

    float acc[8][8];
    #pragma unroll
    for (int i = 0; i < 8; i++)
        #pragma unroll
        for (int j = 0; j < 8; j++) acc[i][j] = 0.f;

    float4 a_nxt = *(const float4*)Ag;
    float4 b_nxt = *(const float4*)Bg;

    for (int k0 = 0; k0 < K; k0 += BKK) {
        As[lcol + 0][lrow] = a_nxt.x;
        As[lcol + 1][lrow] = a_nxt.y;
        As[lcol + 2][lrow] = a_nxt.z;
        As[lcol + 3][lrow] = a_nxt.w;
        Bs[lcol + 0][lrow] = b_nxt.x;
        Bs[lcol + 1][lrow] = b_nxt.y;
        Bs[lcol + 2][lrow] = b_nxt.z;
        Bs[lcol + 3][lrow] = b_nxt.w;
        __syncthreads();

        if (k0 + BKK < K) {
            a_nxt = *(const float4*)(Ag + k0 + BKK);
            b_nxt = *(const float4*)(Bg + k0 + BKK);
        }

        #pragma unroll
        for (int kk = 0; kk < BKK; ++kk) {
            float ar[8], br[8];
            *(float4*)&ar[0] = *(const float4*)&As[kk][ty * 8];
            *(float4*)&ar[4] = *(const float4*)&As[kk][ty * 8 + 4];
            *(float4*)&br[0] = *(const float4*)&Bs[kk][tx * 8];
            *(float4*)&br[4] = *(const float4*)&Bs[kk][tx * 8 + 4];
            #pragma unroll
            for (int i = 0; i < 8; i++)
                #pragma unroll
                for (int j = 0; j < 8; j++)
                    acc[i][j] = fmaf(ar[i], br[j], acc[i][j]);
        }
        __syncthreads();
    }

    #pragma unroll
    for (int i = 0; i < 8; i++) {
        float* Cr = C + (size_t)(bm + ty * 8 + i) * N + bn + tx * 8;
        float4 c0 = make_float4(acc[i][0], acc[i][1], acc[i][2], acc[i][3]);
        float4 c1 = make_float4(acc[i][4], acc[i][5], acc[i][6], acc[i][7]);
        *(float4*)&Cr[0] = c0;
        *(float4*)&Cr[4] = c1;
    }
}

// ---------------------------------------------------------------------------
// Flash-attention with StreamingLLM mask (sink n_init, window n_local).
// BQ=32 queries/block, BKV=32 keys/tile, 128 threads.
// Thread (ty 0..7, tx 0..15): 4 query rows, 2 score cols, 8 output d-cols.
// K staged transposed [d][kk] (stride 33, conflict-free); V natural [kk][d]
// (stride 132); both share one smem buffer (sequential use).
// ---------------------------------------------------------------------------
#define BQ  32
#define BKV 32

__global__ __launch_bounds__(128) void attn_kernel(
    const float* __restrict__ Q, const float* __restrict__ K,
    const float* __restrict__ V, float* __restrict__ Ob,
    const int* __restrict__ n_init_p, const int* __restrict__ n_local_p) {

    const int h   = blockIdx.y;
    const int q0  = blockIdx.x * BQ;
    const int hkv = h / (NH / NKV);
    const int n_init  = *n_init_p;
    const int n_local = *n_local_p;

    __shared__ float Qs[BQ][HD];            // 16 KB
    __shared__ float KV[4224];              // max(128*33, 32*132) floats = 16.5 KB
    __shared__ float Ps[BQ][BKV + 1];       // 4.2 KB

    const int tid = threadIdx.x;
    const int tx  = tid & 15;
    const int ty  = tid >> 4;

    // Load Q tile (coalesced float4)
    #pragma unroll
    for (int e = tid; e < BQ * HD / 4; e += 128) {
        int r = e >> 5;
        int c = (e & 31) * 4;
        *(float4*)&Qs[r][c] =
            *(const float4*)&Q[(size_t)(q0 + r) * HID + h * HD + c];
    }

    float m_i[4], l_i[4], o_acc[4][8];
    #pragma unroll
    for (int i = 0; i < 4; i++) {
        m_i[i] = -1e30f;
        l_i[i] = 0.f;
        #pragma unroll
        for (int j = 0; j < 8; j++) o_acc[i][j] = 0.f;
    }
    __syncthreads();

    const int   kb_max = (q0 + BQ - 1) / BKV;
    const float scale  = 0.08838834764831845f;  // 1/sqrt(128)

    for (int kb = 0; kb <= kb_max; ++kb) {
        const int k0 = kb * BKV;
        // Skip tiles fully outside sink + sliding window
        if (k0 >= n_init && (q0 - (k0 + BKV - 1)) >= n_local) continue;

        // Stage K transposed: KV[d*33 + kk]
        #pragma unroll
        for (int e = tid; e < BKV * HD; e += 128) {
            int kk = e >> 7;
            int d  = e & 127;
            KV[d * (BKV + 1) + kk] =
                K[(size_t)(k0 + kk) * KVDIM + hkv * HD + d];
        }
        __syncthreads();

        // S = Q @ K^T for this tile
        float s[4][2] = {};
        #pragma unroll 4
        for (int d = 0; d < HD; ++d) {
            float b0 = KV[d * (BKV + 1) + 2 * tx];
            float b1 = KV[d * (BKV + 1) + 2 * tx + 1];
            #pragma unroll
            for (int i = 0; i < 4; i++) {
                float a = Qs[4 * ty + i][d];
                s[i][0] = fmaf(a, b0, s[i][0]);
                s[i][1] = fmaf(a, b1, s[i][1]);
            }
        }

        // Mask + online softmax (row groups = 16 lanes sharing ty)
        #pragma unroll
        for (int i = 0; i < 4; i++) {
            int qi = q0 + 4 * ty + i;
            #pragma unroll
            for (int j = 0; j < 2; j++) {
                int kj = k0 + 2 * tx + j;
                bool ok = (kj <= qi) && (kj < n_init || (qi - kj) < n_local);
                s[i][j] = ok ? s[i][j] * scale : -1e30f;
            }
            float tm = fmaxf(s[i][0], s[i][1]);
            #pragma unroll
            for (int off = 8; off >= 1; off >>= 1)
                tm = fmaxf(tm, __shfl_xor_sync(0xffffffffu, tm, off, 16));
            float mn    = fmaxf(m_i[i], tm);
            float alpha = __expf(m_i[i] - mn);
            float p0 = (s[i][0] <= -1e29f) ? 0.f : __expf(s[i][0] - mn);
            float p1 = (s[i][1] <= -1e29f) ? 0.f : __expf(s[i][1] - mn);
            float rs = p0 + p1;
            #pragma unroll
            for (int off = 8; off >= 1; off >>= 1)
                rs += __shfl_xor_sync(0xffffffffu, rs, off, 16);
            l_i[i] = l_i[i] * alpha + rs;
            m_i[i] = mn;
            #pragma unroll
            for (int j = 0; j < 8; j++) o_acc[i][j] *= alpha;
            Ps[4 * ty + i][2 * tx]     = p0;
            Ps[4 * ty + i][2 * tx + 1] = p1;
        }
        __syncthreads();  // P written; all K reads done

        // Stage V natural: KV[kk*132 + d]
        #pragma unroll
        for (int e = tid; e < BKV * HD; e += 128) {
            int kk = e >> 7;
            int d  = e & 127;
            KV[kk * (HD + 4) + d] =
                V[(size_t)(k0 + kk) * KVDIM + hkv * HD + d];
        }
        __syncthreads();

        // O += P @ V  (d-cols tx + 16*j: conflict-free scalar LDS)
        #pragma unroll 2
        for (int kk = 0; kk < BKV; ++kk) {
            float pr[4];
            #pragma unroll
            for (int i = 0; i < 4; i++) pr[i] = Ps[4 * ty + i][kk];
            #pragma unroll
            for (int j = 0; j < 8; j++) {
                float vv = KV[kk * (HD + 4) + tx + 16 * j];
                #pragma unroll
                for (int i = 0; i < 4; i++)
                    o_acc[i][j] = fmaf(pr[i], vv, o_acc[i][j]);
            }
        }
        __syncthreads();  // before next tile overwrites KV
    }

    // Epilogue: normalize and write attn output [s, h*128 + d]
    #pragma unroll
    for (int i = 0; i < 4; i++) {
        float inv = 1.f / l_i[i];
        #pragma unroll
        for (int j = 0; j < 8; j++)
            Ob[(size_t)(q0 + 4 * ty + i) * HID + h * HD + tx + 16 * j] =
                o_acc[i][j] * inv;
    }
}

// ---------------------------------------------------------------------------
extern "C" void kernel_launch(void* const* d_in, const int* in_sizes, int n_in,
                              void* d_out, int out_size) {
    const float* hs = (const float*)d_in[0];
    const float* Wq = (const float*)d_in[1];
    const float* Wk = (const float*)d_in[2];
    const float* Wv = (const float*)d_in[3];
    const float* Wo = (const float*)d_in[4];
    const int* n_init  = (const int*)d_in[5];   // low 32 bits valid for i32/i64
    const int* n_local = (const int*)d_in[6];
    float* out = (float*)d_out;

    float *q, *k, *v, *attn;
    cudaGetSymbolAddress((void**)&q,    g_q);
    cudaGetSymbolAddress((void**)&k,    g_k);
    cudaGetSymbolAddress((void**)&v,    g_v);
    cudaGetSymbolAddress((void**)&attn, g_attn);

    // QKV projections
    gemm_nt<<<dim3(HID / BN,   S_LEN / BM), 256>>>(hs, Wq, q, S_LEN, HID,   HID);
    gemm_nt<<<dim3(KVDIM / BN, S_LEN / BM), 256>>>(hs, Wk, k, S_LEN, KVDIM, HID);
    gemm_nt<<<dim3(KVDIM / BN, S_LEN / BM), 256>>>(hs, Wv, v, S_LEN, KVDIM, HID);

    // Streaming attention
    attn_kernel<<<dim3(S_LEN / BQ, NH), 128>>>(q, k, v, attn, n_init, n_local);

    // Output projection
    gemm_nt<<<dim3(HID / BN, S_LEN / BM), 256>>>(attn, Wo, out, S_LEN, HID, HID);
}

// round 2
// speedup vs baseline: 2.1142x; 2.1142x over previous
#include <cuda_runtime.h>
#include <cuda_bf16.h>
#include <math.h>
#include <stdint.h>

#define S_LEN 2048
#define HID   4096
#define NH    32
#define NKV   8
#define HD    128
#define KVDIM (NKV * HD)   // 1024

// Scratch (allocations are forbidden; __device__ globals are the sanctioned path)
__device__ float g_q[S_LEN * HID];
__device__ float g_k[S_LEN * KVDIM];
__device__ float g_v[S_LEN * KVDIM];
__device__ float g_attn[S_LEN * HID];

// ---------------------------------------------------------------------------
// TF32 tensor-core GEMM: C[M,N] = A[M,K] @ B[N,K]^T  (torch Linear)
// CTA tile 128x128x16, 256 threads (8 warps, 2x4), warp tile 64x32.
// cp.async double-buffered staging; smem row stride 20 floats (80B):
//   - 16B aligned for cp.async
//   - conflict-free for the m16n8k8 fragment LDS pattern
// ---------------------------------------------------------------------------
#define GBM 128
#define GBN 128
#define GBK 16
#define SST 20   // smem row stride in floats

__device__ __forceinline__ void cp_async16(void* smem, const void* gptr) {
    uint32_t s = (uint32_t)__cvta_generic_to_shared(smem);
    asm volatile("cp.async.cg.shared.global [%0], [%1], 16;\n" :: "r"(s), "l"(gptr));
}

__device__ __forceinline__ uint32_t f2tf(float x) {
    uint32_t u;
    asm("cvt.rna.tf32.f32 %0, %1;" : "=r"(u) : "f"(x));
    return u;
}

__device__ __forceinline__ void mma_tf32(float c[4], const uint32_t a[4],
                                         const uint32_t b[2]) {
    asm volatile(
        "mma.sync.aligned.m16n8k8.row.col.f32.tf32.tf32.f32 "
        "{%0,%1,%2,%3},{%4,%5,%6,%7},{%8,%9},{%0,%1,%2,%3};"
        : "+f"(c[0]), "+f"(c[1]), "+f"(c[2]), "+f"(c[3])
        : "r"(a[0]), "r"(a[1]), "r"(a[2]), "r"(a[3]), "r"(b[0]), "r"(b[1]));
}

__global__ __launch_bounds__(256, 2) void gemm_tf32(const float* __restrict__ A,
                                                    const float* __restrict__ B,
                                                    float* __restrict__ C,
                                                    int M, int N, int K) {
    __shared__ float As[2][GBM][SST];
    __shared__ float Bs[2][GBN][SST];

    const int bm   = blockIdx.y * GBM;
    const int bn   = blockIdx.x * GBN;
    const int tid  = threadIdx.x;
    const int warp = tid >> 5;
    const int lane = tid & 31;
    const int wm   = (warp & 1) * 64;   // warp row offset
    const int wn   = (warp >> 1) * 32;  // warp col offset
    const int g    = lane >> 2;         // group id 0..7
    const int t    = lane & 3;          // thread-in-group 0..3

    // Each thread copies 2x float4 for A and 2x for B per tile.
    const int l0 = tid, l1 = tid + 256;
    const int ar0 = l0 >> 2, ac0 = (l0 & 3) << 2;
    const int ar1 = l1 >> 2, ac1 = (l1 & 3) << 2;

    float c[4][4][4];
    #pragma unroll
    for (int mt = 0; mt < 4; mt++)
        #pragma unroll
        for (int nt = 0; nt < 4; nt++)
            #pragma unroll
            for (int i = 0; i < 4; i++) c[mt][nt][i] = 0.f;

    // Prologue: stage 0
    {
        cp_async16(&As[0][ar0][ac0], A + (size_t)(bm + ar0) * K + ac0);
        cp_async16(&As[0][ar1][ac1], A + (size_t)(bm + ar1) * K + ac1);
        cp_async16(&Bs[0][ar0][ac0], B + (size_t)(bn + ar0) * K + ac0);
        cp_async16(&Bs[0][ar1][ac1], B + (size_t)(bn + ar1) * K + ac1);
        asm volatile("cp.async.commit_group;\n" ::);
    }

    const int KT = K / GBK;
    for (int kt = 0; kt < KT; ++kt) {
        asm volatile("cp.async.wait_group 0;\n" ::);
        __syncthreads();

        if (kt + 1 < KT) {
            const int s2 = (kt + 1) & 1;
            const int k0 = (kt + 1) * GBK;
            cp_async16(&As[s2][ar0][ac0], A + (size_t)(bm + ar0) * K + k0 + ac0);
            cp_async16(&As[s2][ar1][ac1], A + (size_t)(bm + ar1) * K + k0 + ac1);
            cp_async16(&Bs[s2][ar0][ac0], B + (size_t)(bn + ar0) * K + k0 + ac0);
            cp_async16(&Bs[s2][ar1][ac1], B + (size_t)(bn + ar1) * K + k0 + ac1);
            asm volatile("cp.async.commit_group;\n" ::);
        }

        const int s = kt & 1;
        #pragma unroll
        for (int kk = 0; kk < GBK; kk += 8) {
            uint32_t af[4][4], bf[4][2];
            #pragma unroll
            for (int mt = 0; mt < 4; mt++) {
                const int r = wm + mt * 16 + g;
                af[mt][0] = f2tf(As[s][r][kk + t]);
                af[mt][1] = f2tf(As[s][r + 8][kk + t]);
                af[mt][2] = f2tf(As[s][r][kk + t + 4]);
                af[mt][3] = f2tf(As[s][r + 8][kk + t + 4]);
            }
            #pragma unroll
            for (int nt = 0; nt < 4; nt++) {
                const int cc = wn + nt * 8 + g;
                bf[nt][0] = f2tf(Bs[s][cc][kk + t]);
                bf[nt][1] = f2tf(Bs[s][cc][kk + t + 4]);
            }
            #pragma unroll
            for (int mt = 0; mt < 4; mt++)
                #pragma unroll
                for (int nt = 0; nt < 4; nt++)
                    mma_tf32(c[mt][nt], af[mt], bf[nt]);
        }
    }

    // Epilogue
    #pragma unroll
    for (int mt = 0; mt < 4; mt++) {
        #pragma unroll
        for (int nt = 0; nt < 4; nt++) {
            const int row = bm + wm + mt * 16 + g;
            const int col = bn + wn + nt * 8 + 2 * t;
            float2 v0 = make_float2(c[mt][nt][0], c[mt][nt][1]);
            float2 v1 = make_float2(c[mt][nt][2], c[mt][nt][3]);
            *(float2*)&C[(size_t)row * N + col]       = v0;
            *(float2*)&C[(size_t)(row + 8) * N + col] = v1;
        }
    }
}

// ---------------------------------------------------------------------------
// Flash-attention with StreamingLLM mask (sink n_init, window n_local).
// (unchanged from round 1 — isolated change for attribution)
// ---------------------------------------------------------------------------
#define BQ  32
#define BKV 32

__global__ __launch_bounds__(128) void attn_kernel(
    const float* __restrict__ Q, const float* __restrict__ K,
    const float* __restrict__ V, float* __restrict__ Ob,
    const int* __restrict__ n_init_p, const int* __restrict__ n_local_p) {

    const int h   = blockIdx.y;
    const int q0  = blockIdx.x * BQ;
    const int hkv = h / (NH / NKV);
    const int n_init  = *n_init_p;
    const int n_local = *n_local_p;

    __shared__ float Qs[BQ][HD];
    __shared__ float KV[4224];
    __shared__ float Ps[BQ][BKV + 1];

    const int tid = threadIdx.x;
    const int tx  = tid & 15;
    const int ty  = tid >> 4;

    #pragma unroll
    for (int e = tid; e < BQ * HD / 4; e += 128) {
        int r = e >> 5;
        int cc = (e & 31) * 4;
        *(float4*)&Qs[r][cc] =
            *(const float4*)&Q[(size_t)(q0 + r) * HID + h * HD + cc];
    }

    float m_i[4], l_i[4], o_acc[4][8];
    #pragma unroll
    for (int i = 0; i < 4; i++) {
        m_i[i] = -1e30f;
        l_i[i] = 0.f;
        #pragma unroll
        for (int j = 0; j < 8; j++) o_acc[i][j] = 0.f;
    }
    __syncthreads();

    const int   kb_max = (q0 + BQ - 1) / BKV;
    const float scale  = 0.08838834764831845f;

    for (int kb = 0; kb <= kb_max; ++kb) {
        const int k0 = kb * BKV;
        if (k0 >= n_init && (q0 - (k0 + BKV - 1)) >= n_local) continue;

        #pragma unroll
        for (int e = tid; e < BKV * HD; e += 128) {
            int kk = e >> 7;
            int d  = e & 127;
            KV[d * (BKV + 1) + kk] =
                K[(size_t)(k0 + kk) * KVDIM + hkv * HD + d];
        }
        __syncthreads();

        float s[4][2] = {};
        #pragma unroll 4
        for (int d = 0; d < HD; ++d) {
            float b0 = KV[d * (BKV + 1) + 2 * tx];
            float b1 = KV[d * (BKV + 1) + 2 * tx + 1];
            #pragma unroll
            for (int i = 0; i < 4; i++) {
                float a = Qs[4 * ty + i][d];
                s[i][0] = fmaf(a, b0, s[i][0]);
                s[i][1] = fmaf(a, b1, s[i][1]);
            }
        }

        #pragma unroll
        for (int i = 0; i < 4; i++) {
            int qi = q0 + 4 * ty + i;
            #pragma unroll
            for (int j = 0; j < 2; j++) {
                int kj = k0 + 2 * tx + j;
                bool ok = (kj <= qi) && (kj < n_init || (qi - kj) < n_local);
                s[i][j] = ok ? s[i][j] * scale : -1e30f;
            }
            float tm = fmaxf(s[i][0], s[i][1]);
            #pragma unroll
            for (int off = 8; off >= 1; off >>= 1)
                tm = fmaxf(tm, __shfl_xor_sync(0xffffffffu, tm, off, 16));
            float mn    = fmaxf(m_i[i], tm);
            float alpha = __expf(m_i[i] - mn);
            float p0 = (s[i][0] <= -1e29f) ? 0.f : __expf(s[i][0] - mn);
            float p1 = (s[i][1] <= -1e29f) ? 0.f : __expf(s[i][1] - mn);
            float rs = p0 + p1;
            #pragma unroll
            for (int off = 8; off >= 1; off >>= 1)
                rs += __shfl_xor_sync(0xffffffffu, rs, off, 16);
            l_i[i] = l_i[i] * alpha + rs;
            m_i[i] = mn;
            #pragma unroll
            for (int j = 0; j < 8; j++) o_acc[i][j] *= alpha;
            Ps[4 * ty + i][2 * tx]     = p0;
            Ps[4 * ty + i][2 * tx + 1] = p1;
        }
        __syncthreads();

        #pragma unroll
        for (int e = tid; e < BKV * HD; e += 128) {
            int kk = e >> 7;
            int d  = e & 127;
            KV[kk * (HD + 4) + d] =
                V[(size_t)(k0 + kk) * KVDIM + hkv * HD + d];
        }
        __syncthreads();

        #pragma unroll 2
        for (int kk = 0; kk < BKV; ++kk) {
            float pr[4];
            #pragma unroll
            for (int i = 0; i < 4; i++) pr[i] = Ps[4 * ty + i][kk];
            #pragma unroll
            for (int j = 0; j < 8; j++) {
                float vv = KV[kk * (HD + 4) + tx + 16 * j];
                #pragma unroll
                for (int i = 0; i < 4; i++)
                    o_acc[i][j] = fmaf(pr[i], vv, o_acc[i][j]);
            }
        }
        __syncthreads();
    }

    #pragma unroll
    for (int i = 0; i < 4; i++) {
        float inv = 1.f / l_i[i];
        #pragma unroll
        for (int j = 0; j < 8; j++)
            Ob[(size_t)(q0 + 4 * ty + i) * HID + h * HD + tx + 16 * j] =
                o_acc[i][j] * inv;
    }
}

// ---------------------------------------------------------------------------
extern "C" void kernel_launch(void* const* d_in, const int* in_sizes, int n_in,
                              void* d_out, int out_size) {
    const float* hs = (const float*)d_in[0];
    const float* Wq = (const float*)d_in[1];
    const float* Wk = (const float*)d_in[2];
    const float* Wv = (const float*)d_in[3];
    const float* Wo = (const float*)d_in[4];
    const int* n_init  = (const int*)d_in[5];
    const int* n_local = (const int*)d_in[6];
    float* out = (float*)d_out;

    float *q, *k, *v, *attn;
    cudaGetSymbolAddress((void**)&q,    g_q);
    cudaGetSymbolAddress((void**)&k,    g_k);
    cudaGetSymbolAddress((void**)&v,    g_v);
    cudaGetSymbolAddress((void**)&attn, g_attn);

    // QKV projections (TF32 tensor cores)
    gemm_tf32<<<dim3(HID / GBN,   S_LEN / GBM), 256>>>(hs, Wq, q, S_LEN, HID,   HID);
    gemm_tf32<<<dim3(KVDIM / GBN, S_LEN / GBM), 256>>>(hs, Wk, k, S_LEN, KVDIM, HID);
    gemm_tf32<<<dim3(KVDIM / GBN, S_LEN / GBM), 256>>>(hs, Wv, v, S_LEN, KVDIM, HID);

    // Streaming attention
    attn_kernel<<<dim3(S_LEN / BQ, NH), 128>>>(q, k, v, attn, n_init, n_local);

    // Output projection
    gemm_tf32<<<dim3(HID / GBN, S_LEN / GBM), 256>>>(attn, Wo, out, S_LEN, HID, HID);
}

// round 3
// speedup vs baseline: 2.7677x; 1.3091x over previous
#include <cuda_runtime.h>
#include <cuda_bf16.h>
#include <math.h>
#include <stdint.h>

#define S_LEN 2048
#define HID   4096
#define NH    32
#define NKV   8
#define HD    128
#define KVDIM (NKV * HD)   // 1024

__device__ float g_q[S_LEN * HID];
__device__ float g_k[S_LEN * KVDIM];
__device__ float g_v[S_LEN * KVDIM];
__device__ float g_attn[S_LEN * HID];

// ---------------------------------------------------------------------------
// TF32 tensor-core GEMM (unchanged from round 2)
// ---------------------------------------------------------------------------
#define GBM 128
#define GBN 128
#define GBK 16
#define SST 20

__device__ __forceinline__ void cp_async16(void* smem, const void* gptr) {
    uint32_t s = (uint32_t)__cvta_generic_to_shared(smem);
    asm volatile("cp.async.cg.shared.global [%0], [%1], 16;\n" :: "r"(s), "l"(gptr));
}

__device__ __forceinline__ uint32_t f2tf(float x) {
    uint32_t u;
    asm("cvt.rna.tf32.f32 %0, %1;" : "=r"(u) : "f"(x));
    return u;
}

__device__ __forceinline__ void mma_tf32(float c[4], const uint32_t a[4],
                                         const uint32_t b[2]) {
    asm volatile(
        "mma.sync.aligned.m16n8k8.row.col.f32.tf32.tf32.f32 "
        "{%0,%1,%2,%3},{%4,%5,%6,%7},{%8,%9},{%0,%1,%2,%3};"
        : "+f"(c[0]), "+f"(c[1]), "+f"(c[2]), "+f"(c[3])
        : "r"(a[0]), "r"(a[1]), "r"(a[2]), "r"(a[3]), "r"(b[0]), "r"(b[1]));
}

__global__ __launch_bounds__(256, 2) void gemm_tf32(const float* __restrict__ A,
                                                    const float* __restrict__ B,
                                                    float* __restrict__ C,
                                                    int M, int N, int K) {
    __shared__ float As[2][GBM][SST];
    __shared__ float Bs[2][GBN][SST];

    const int bm   = blockIdx.y * GBM;
    const int bn   = blockIdx.x * GBN;
    const int tid  = threadIdx.x;
    const int warp = tid >> 5;
    const int lane = tid & 31;
    const int wm   = (warp & 1) * 64;
    const int wn   = (warp >> 1) * 32;
    const int g    = lane >> 2;
    const int t    = lane & 3;

    const int l0 = tid, l1 = tid + 256;
    const int ar0 = l0 >> 2, ac0 = (l0 & 3) << 2;
    const int ar1 = l1 >> 2, ac1 = (l1 & 3) << 2;

    float c[4][4][4];
    #pragma unroll
    for (int mt = 0; mt < 4; mt++)
        #pragma unroll
        for (int nt = 0; nt < 4; nt++)
            #pragma unroll
            for (int i = 0; i < 4; i++) c[mt][nt][i] = 0.f;

    {
        cp_async16(&As[0][ar0][ac0], A + (size_t)(bm + ar0) * K + ac0);
        cp_async16(&As[0][ar1][ac1], A + (size_t)(bm + ar1) * K + ac1);
        cp_async16(&Bs[0][ar0][ac0], B + (size_t)(bn + ar0) * K + ac0);
        cp_async16(&Bs[0][ar1][ac1], B + (size_t)(bn + ar1) * K + ac1);
        asm volatile("cp.async.commit_group;\n" ::);
    }

    const int KT = K / GBK;
    for (int kt = 0; kt < KT; ++kt) {
        asm volatile("cp.async.wait_group 0;\n" ::);
        __syncthreads();

        if (kt + 1 < KT) {
            const int s2 = (kt + 1) & 1;
            const int k0 = (kt + 1) * GBK;
            cp_async16(&As[s2][ar0][ac0], A + (size_t)(bm + ar0) * K + k0 + ac0);
            cp_async16(&As[s2][ar1][ac1], A + (size_t)(bm + ar1) * K + k0 + ac1);
            cp_async16(&Bs[s2][ar0][ac0], B + (size_t)(bn + ar0) * K + k0 + ac0);
            cp_async16(&Bs[s2][ar1][ac1], B + (size_t)(bn + ar1) * K + k0 + ac1);
            asm volatile("cp.async.commit_group;\n" ::);
        }

        const int s = kt & 1;
        #pragma unroll
        for (int kk = 0; kk < GBK; kk += 8) {
            uint32_t af[4][4], bf[4][2];
            #pragma unroll
            for (int mt = 0; mt < 4; mt++) {
                const int r = wm + mt * 16 + g;
                af[mt][0] = f2tf(As[s][r][kk + t]);
                af[mt][1] = f2tf(As[s][r + 8][kk + t]);
                af[mt][2] = f2tf(As[s][r][kk + t + 4]);
                af[mt][3] = f2tf(As[s][r + 8][kk + t + 4]);
            }
            #pragma unroll
            for (int nt = 0; nt < 4; nt++) {
                const int cc = wn + nt * 8 + g;
                bf[nt][0] = f2tf(Bs[s][cc][kk + t]);
                bf[nt][1] = f2tf(Bs[s][cc][kk + t + 4]);
            }
            #pragma unroll
            for (int mt = 0; mt < 4; mt++)
                #pragma unroll
                for (int nt = 0; nt < 4; nt++)
                    mma_tf32(c[mt][nt], af[mt], bf[nt]);
        }
    }

    #pragma unroll
    for (int mt = 0; mt < 4; mt++) {
        #pragma unroll
        for (int nt = 0; nt < 4; nt++) {
            const int row = bm + wm + mt * 16 + g;
            const int col = bn + wn + nt * 8 + 2 * t;
            float2 v0 = make_float2(c[mt][nt][0], c[mt][nt][1]);
            float2 v1 = make_float2(c[mt][nt][2], c[mt][nt][3]);
            *(float2*)&C[(size_t)row * N + col]       = v0;
            *(float2*)&C[(size_t)(row + 8) * N + col] = v1;
        }
    }
}

// ---------------------------------------------------------------------------
// Attention: split-bf16 (hi+lo) 3-term MMA flash attention.
// BQ=128, BKV=64, 256 threads (8 warps); warp w owns rows w*16..w*16+15,
// full tile width. QK^T and P@V via mma.m16n8k16 bf16 with fp32 accum:
//   X @ Y ~= Xh@Yh + Xh@Yl + Xl@Yh   (error ~2^-17, preserves logits)
// P fragments rebuilt from S accumulator registers (no smem round-trip).
// ---------------------------------------------------------------------------
#define ABQ  128
#define ABK  64
#define APAD 136   // bf16 row stride (272B: 16B-aligned, ldmatrix conflict-free)
#define ASMEM ((2 * ABQ + 4 * ABK) * APAD * 2)   // 139264 bytes

__device__ __forceinline__ void ldsm_x4(uint32_t r[4], const void* p) {
    uint32_t a = (uint32_t)__cvta_generic_to_shared(p);
    asm volatile("ldmatrix.sync.aligned.m8n8.x4.shared.b16 {%0,%1,%2,%3}, [%4];"
                 : "=r"(r[0]), "=r"(r[1]), "=r"(r[2]), "=r"(r[3]) : "r"(a));
}

__device__ __forceinline__ void ldsm_x4_t(uint32_t r[4], const void* p) {
    uint32_t a = (uint32_t)__cvta_generic_to_shared(p);
    asm volatile("ldmatrix.sync.aligned.m8n8.x4.trans.shared.b16 {%0,%1,%2,%3}, [%4];"
                 : "=r"(r[0]), "=r"(r[1]), "=r"(r[2]), "=r"(r[3]) : "r"(a));
}

__device__ __forceinline__ void mma_bf16(float c[4], const uint32_t a[4],
                                         uint32_t b0, uint32_t b1) {
    asm volatile(
        "mma.sync.aligned.m16n8k16.row.col.f32.bf16.bf16.f32 "
        "{%0,%1,%2,%3},{%4,%5,%6,%7},{%8,%9},{%0,%1,%2,%3};"
        : "+f"(c[0]), "+f"(c[1]), "+f"(c[2]), "+f"(c[3])
        : "r"(a[0]), "r"(a[1]), "r"(a[2]), "r"(a[3]), "r"(b0), "r"(b1));
}

// Split 4 floats into bf16 hi/lo pairs and store (two bf162 stores each).
__device__ __forceinline__ void split_store4(__nv_bfloat16* H, __nv_bfloat16* L,
                                             int off, float4 x) {
    __nv_bfloat162 hA = __floats2bfloat162_rn(x.x, x.y);
    __nv_bfloat162 hB = __floats2bfloat162_rn(x.z, x.w);
    float r0 = x.x - __low2float(hA),  r1 = x.y - __high2float(hA);
    float r2 = x.z - __low2float(hB),  r3 = x.w - __high2float(hB);
    __nv_bfloat162 lA = __floats2bfloat162_rn(r0, r1);
    __nv_bfloat162 lB = __floats2bfloat162_rn(r2, r3);
    *(__nv_bfloat162*)&H[off]     = hA;
    *(__nv_bfloat162*)&H[off + 2] = hB;
    *(__nv_bfloat162*)&L[off]     = lA;
    *(__nv_bfloat162*)&L[off + 2] = lB;
}

__global__ __launch_bounds__(256, 1) void attn_mma(
    const float* __restrict__ Q, const float* __restrict__ Kg,
    const float* __restrict__ Vg, float* __restrict__ Ob,
    const int* __restrict__ n_init_p, const int* __restrict__ n_local_p) {

    extern __shared__ __nv_bfloat16 smb[];
    __nv_bfloat16* Qh = smb;
    __nv_bfloat16* Ql = Qh + ABQ * APAD;
    __nv_bfloat16* Kh = Ql + ABQ * APAD;
    __nv_bfloat16* Kl = Kh + ABK * APAD;
    __nv_bfloat16* Vh = Kl + ABK * APAD;
    __nv_bfloat16* Vl = Vh + ABK * APAD;

    const int h   = blockIdx.y;
    const int q0  = blockIdx.x * ABQ;
    const int hkv = h >> 2;               // NH/NKV = 4
    const int n_init  = *n_init_p;
    const int n_local = *n_local_p;

    const int tid  = threadIdx.x;
    const int warp = tid >> 5;
    const int lane = tid & 31;
    const int g    = lane >> 2;
    const int t    = lane & 3;
    const int grp  = lane >> 3;           // 0..3, for B-matrix ldmatrix addressing

    // ---- stage Q (split hi/lo) ----
    #pragma unroll
    for (int it = 0; it < 16; ++it) {
        int idx = tid + it * 256;                    // 0..4095 float4s
        int r = idx >> 5, c4 = (idx & 31) << 2;
        float4 x = *(const float4*)&Q[(size_t)(q0 + r) * HID + h * HD + c4];
        split_store4(Qh, Ql, r * APAD + c4, x);
    }

    float o[16][4];
    float m_i[2] = {-1e30f, -1e30f};
    float l_i[2] = {0.f, 0.f};
    #pragma unroll
    for (int nb = 0; nb < 16; nb++)
        #pragma unroll
        for (int j = 0; j < 4; j++) o[nb][j] = 0.f;

    const int   row0  = q0 + warp * 16 + g;
    const int   kb_max = (q0 + ABQ - 1) / ABK;
    const float scale  = 0.08838834764831845f;

    for (int kb = 0; kb <= kb_max; ++kb) {
        const int k0 = kb * ABK;
        if (k0 >= n_init && (q0 - (k0 + ABK - 1)) >= n_local) continue;

        __syncthreads();   // previous tile's V reads done before restaging
        // ---- stage K and V tiles (split hi/lo) ----
        #pragma unroll
        for (int it = 0; it < 8; ++it) {
            int idx = tid + it * 256;                // 0..2047 float4s
            int r = idx >> 5, c4 = (idx & 31) << 2;
            float4 xk = *(const float4*)&Kg[(size_t)(k0 + r) * KVDIM + hkv * HD + c4];
            split_store4(Kh, Kl, r * APAD + c4, xk);
            float4 xv = *(const float4*)&Vg[(size_t)(k0 + r) * KVDIM + hkv * HD + c4];
            split_store4(Vh, Vl, r * APAD + c4, xv);
        }
        __syncthreads();

        // ---- S = Q @ K^T (3-term split) ----
        float sc[8][4];
        #pragma unroll
        for (int nb = 0; nb < 8; nb++)
            #pragma unroll
            for (int j = 0; j < 4; j++) sc[nb][j] = 0.f;

        #pragma unroll
        for (int kk = 0; kk < 8; ++kk) {             // d = 128 in k16 steps
            uint32_t qa_h[4], qa_l[4];
            const int aoff = (warp * 16 + (lane & 15)) * APAD + kk * 16 + (lane >> 4) * 8;
            ldsm_x4(qa_h, Qh + aoff);
            ldsm_x4(qa_l, Ql + aoff);
            #pragma unroll
            for (int nbp = 0; nbp < 4; ++nbp) {      // nb pairs (2 per ldmatrix.x4)
                uint32_t kb_h[4], kb_l[4];
                const int boff = (nbp * 16 + (grp >> 1) * 8 + (lane & 7)) * APAD
                               + kk * 16 + (grp & 1) * 8;
                ldsm_x4(kb_h, Kh + boff);
                ldsm_x4(kb_l, Kl + boff);
                mma_bf16(sc[2 * nbp],     qa_h, kb_h[0], kb_h[1]);
                mma_bf16(sc[2 * nbp],     qa_h, kb_l[0], kb_l[1]);
                mma_bf16(sc[2 * nbp],     qa_l, kb_h[0], kb_h[1]);
                mma_bf16(sc[2 * nbp + 1], qa_h, kb_h[2], kb_h[3]);
                mma_bf16(sc[2 * nbp + 1], qa_h, kb_l[2], kb_l[3]);
                mma_bf16(sc[2 * nbp + 1], qa_l, kb_h[2], kb_h[3]);
            }
        }

        // ---- mask + online softmax (rows g and g+8 of this warp) ----
        float tm0 = -1e30f, tm1 = -1e30f;
        #pragma unroll
        for (int nb = 0; nb < 8; ++nb) {
            int cb = k0 + nb * 8 + 2 * t;
            #pragma unroll
            for (int j = 0; j < 2; ++j) {
                int cc = cb + j;
                bool ok0 = (cc <= row0)     && (cc < n_init || row0 - cc < n_local);
                bool ok1 = (cc <= row0 + 8) && (cc < n_init || row0 + 8 - cc < n_local);
                sc[nb][j]     = ok0 ? sc[nb][j] * scale     : -1e30f;
                sc[nb][2 + j] = ok1 ? sc[nb][2 + j] * scale : -1e30f;
                tm0 = fmaxf(tm0, sc[nb][j]);
                tm1 = fmaxf(tm1, sc[nb][2 + j]);
            }
        }
        tm0 = fmaxf(tm0, __shfl_xor_sync(0xffffffffu, tm0, 1));
        tm0 = fmaxf(tm0, __shfl_xor_sync(0xffffffffu, tm0, 2));
        tm1 = fmaxf(tm1, __shfl_xor_sync(0xffffffffu, tm1, 1));
        tm1 = fmaxf(tm1, __shfl_xor_sync(0xffffffffu, tm1, 2));

        float mn0 = fmaxf(m_i[0], tm0), mn1 = fmaxf(m_i[1], tm1);
        float al0 = __expf(m_i[0] - mn0), al1 = __expf(m_i[1] - mn1);
        float rs0 = 0.f, rs1 = 0.f;
        #pragma unroll
        for (int nb = 0; nb < 8; ++nb) {
            #pragma unroll
            for (int j = 0; j < 2; ++j) {
                float p0 = __expf(sc[nb][j] - mn0);
                float p1 = __expf(sc[nb][2 + j] - mn1);
                sc[nb][j] = p0;  sc[nb][2 + j] = p1;
                rs0 += p0;  rs1 += p1;
            }
        }
        rs0 += __shfl_xor_sync(0xffffffffu, rs0, 1);
        rs0 += __shfl_xor_sync(0xffffffffu, rs0, 2);
        rs1 += __shfl_xor_sync(0xffffffffu, rs1, 1);
        rs1 += __shfl_xor_sync(0xffffffffu, rs1, 2);
        l_i[0] = l_i[0] * al0 + rs0;  m_i[0] = mn0;
        l_i[1] = l_i[1] * al1 + rs1;  m_i[1] = mn1;
        #pragma unroll
        for (int nb = 0; nb < 16; ++nb) {
            o[nb][0] *= al0;  o[nb][1] *= al0;
            o[nb][2] *= al1;  o[nb][3] *= al1;
        }

        // ---- pack P fragments (hi/lo) straight from S registers ----
        uint32_t ph[8][2], pl[8][2];
        #pragma unroll
        for (int nb = 0; nb < 8; ++nb) {
            __nv_bfloat162 h0 = __floats2bfloat162_rn(sc[nb][0], sc[nb][1]);
            __nv_bfloat162 h1 = __floats2bfloat162_rn(sc[nb][2], sc[nb][3]);
            float r0 = sc[nb][0] - __low2float(h0), r1 = sc[nb][1] - __high2float(h0);
            float r2 = sc[nb][2] - __low2float(h1), r3 = sc[nb][3] - __high2float(h1);
            __nv_bfloat162 q0b = __floats2bfloat162_rn(r0, r1);
            __nv_bfloat162 q1b = __floats2bfloat162_rn(r2, r3);
            ph[nb][0] = *(uint32_t*)&h0;  ph[nb][1] = *(uint32_t*)&h1;
            pl[nb][0] = *(uint32_t*)&q0b; pl[nb][1] = *(uint32_t*)&q1b;
        }

        // ---- O += P @ V (3-term split); V via ldmatrix.trans ----
        #pragma unroll
        for (int ks = 0; ks < 4; ++ks) {             // key dim 64 in k16 steps
            uint32_t aH[4] = { ph[2 * ks][0], ph[2 * ks][1],
                               ph[2 * ks + 1][0], ph[2 * ks + 1][1] };
            uint32_t aL[4] = { pl[2 * ks][0], pl[2 * ks][1],
                               pl[2 * ks + 1][0], pl[2 * ks + 1][1] };
            #pragma unroll
            for (int np = 0; np < 8; ++np) {         // 16 d-nb in pairs
                uint32_t vh[4], vl[4];
                const int voff = (ks * 16 + (grp & 1) * 8 + (lane & 7)) * APAD
                               + (np * 2 + (grp >> 1)) * 8;
                ldsm_x4_t(vh, Vh + voff);
                ldsm_x4_t(vl, Vl + voff);
                mma_bf16(o[2 * np],     aH, vh[0], vh[1]);
                mma_bf16(o[2 * np],     aH, vl[0], vl[1]);
                mma_bf16(o[2 * np],     aL, vh[0], vh[1]);
                mma_bf16(o[2 * np + 1], aH, vh[2], vh[3]);
                mma_bf16(o[2 * np + 1], aH, vl[2], vl[3]);
                mma_bf16(o[2 * np + 1], aL, vh[2], vh[3]);
            }
        }
    }

    // ---- epilogue ----
    float inv0 = 1.f / l_i[0], inv1 = 1.f / l_i[1];
    #pragma unroll
    for (int nb = 0; nb < 16; ++nb) {
        int col = h * HD + nb * 8 + 2 * t;
        float2 v0 = make_float2(o[nb][0] * inv0, o[nb][1] * inv0);
        float2 v1 = make_float2(o[nb][2] * inv1, o[nb][3] * inv1);
        *(float2*)&Ob[(size_t)row0 * HID + col]       = v0;
        *(float2*)&Ob[(size_t)(row0 + 8) * HID + col] = v1;
    }
}

// ---------------------------------------------------------------------------
extern "C" void kernel_launch(void* const* d_in, const int* in_sizes, int n_in,
                              void* d_out, int out_size) {
    const float* hs = (const float*)d_in[0];
    const float* Wq = (const float*)d_in[1];
    const float* Wk = (const float*)d_in[2];
    const float* Wv = (const float*)d_in[3];
    const float* Wo = (const float*)d_in[4];
    const int* n_init  = (const int*)d_in[5];
    const int* n_local = (const int*)d_in[6];
    float* out = (float*)d_out;

    float *q, *k, *v, *attn;
    cudaGetSymbolAddress((void**)&q,    g_q);
    cudaGetSymbolAddress((void**)&k,    g_k);
    cudaGetSymbolAddress((void**)&v,    g_v);
    cudaGetSymbolAddress((void**)&attn, g_attn);

    static int smem_set = 0;
    if (!smem_set) {
        cudaFuncSetAttribute(attn_mma, cudaFuncAttributeMaxDynamicSharedMemorySize,
                             ASMEM);
        smem_set = 1;
    }

    gemm_tf32<<<dim3(HID / GBN,   S_LEN / GBM), 256>>>(hs, Wq, q, S_LEN, HID,   HID);
    gemm_tf32<<<dim3(KVDIM / GBN, S_LEN / GBM), 256>>>(hs, Wk, k, S_LEN, KVDIM, HID);
    gemm_tf32<<<dim3(KVDIM / GBN, S_LEN / GBM), 256>>>(hs, Wv, v, S_LEN, KVDIM, HID);

    attn_mma<<<dim3(S_LEN / ABQ, NH), 256, ASMEM>>>(q, k, v, attn, n_init, n_local);

    gemm_tf32<<<dim3(HID / GBN, S_LEN / GBM), 256>>>(attn, Wo, out, S_LEN, HID, HID);
}

// round 4
// speedup vs baseline: 2.7704x; 1.0010x over previous
#include <cuda_runtime.h>
#include <cuda_bf16.h>
#include <math.h>
#include <stdint.h>

#define S_LEN 2048
#define HID   4096
#define NH    32
#define NKV   8
#define HD    128
#define KVDIM (NKV * HD)   // 1024

__device__ float g_q[S_LEN * HID];
__device__ float g_k[S_LEN * KVDIM];
__device__ float g_v[S_LEN * KVDIM];
__device__ float g_attn[S_LEN * HID];

// ---------------------------------------------------------------------------
// TF32 tensor-core GEMM (unchanged from round 2)
// ---------------------------------------------------------------------------
#define GBM 128
#define GBN 128
#define GBK 16
#define SST 20

__device__ __forceinline__ void cp_async16(void* smem, const void* gptr) {
    uint32_t s = (uint32_t)__cvta_generic_to_shared(smem);
    asm volatile("cp.async.cg.shared.global [%0], [%1], 16;\n" :: "r"(s), "l"(gptr));
}

__device__ __forceinline__ uint32_t f2tf(float x) {
    uint32_t u;
    asm("cvt.rna.tf32.f32 %0, %1;" : "=r"(u) : "f"(x));
    return u;
}

__device__ __forceinline__ void mma_tf32(float c[4], const uint32_t a[4],
                                         const uint32_t b[2]) {
    asm volatile(
        "mma.sync.aligned.m16n8k8.row.col.f32.tf32.tf32.f32 "
        "{%0,%1,%2,%3},{%4,%5,%6,%7},{%8,%9},{%0,%1,%2,%3};"
        : "+f"(c[0]), "+f"(c[1]), "+f"(c[2]), "+f"(c[3])
        : "r"(a[0]), "r"(a[1]), "r"(a[2]), "r"(a[3]), "r"(b[0]), "r"(b[1]));
}

__global__ __launch_bounds__(256, 2) void gemm_tf32(const float* __restrict__ A,
                                                    const float* __restrict__ B,
                                                    float* __restrict__ C,
                                                    int M, int N, int K) {
    __shared__ float As[2][GBM][SST];
    __shared__ float Bs[2][GBN][SST];

    const int bm   = blockIdx.y * GBM;
    const int bn   = blockIdx.x * GBN;
    const int tid  = threadIdx.x;
    const int warp = tid >> 5;
    const int lane = tid & 31;
    const int wm   = (warp & 1) * 64;
    const int wn   = (warp >> 1) * 32;
    const int g    = lane >> 2;
    const int t    = lane & 3;

    const int l0 = tid, l1 = tid + 256;
    const int ar0 = l0 >> 2, ac0 = (l0 & 3) << 2;
    const int ar1 = l1 >> 2, ac1 = (l1 & 3) << 2;

    float c[4][4][4];
    #pragma unroll
    for (int mt = 0; mt < 4; mt++)
        #pragma unroll
        for (int nt = 0; nt < 4; nt++)
            #pragma unroll
            for (int i = 0; i < 4; i++) c[mt][nt][i] = 0.f;

    {
        cp_async16(&As[0][ar0][ac0], A + (size_t)(bm + ar0) * K + ac0);
        cp_async16(&As[0][ar1][ac1], A + (size_t)(bm + ar1) * K + ac1);
        cp_async16(&Bs[0][ar0][ac0], B + (size_t)(bn + ar0) * K + ac0);
        cp_async16(&Bs[0][ar1][ac1], B + (size_t)(bn + ar1) * K + ac1);
        asm volatile("cp.async.commit_group;\n" ::);
    }

    const int KT = K / GBK;
    for (int kt = 0; kt < KT; ++kt) {
        asm volatile("cp.async.wait_group 0;\n" ::);
        __syncthreads();

        if (kt + 1 < KT) {
            const int s2 = (kt + 1) & 1;
            const int k0 = (kt + 1) * GBK;
            cp_async16(&As[s2][ar0][ac0], A + (size_t)(bm + ar0) * K + k0 + ac0);
            cp_async16(&As[s2][ar1][ac1], A + (size_t)(bm + ar1) * K + k0 + ac1);
            cp_async16(&Bs[s2][ar0][ac0], B + (size_t)(bn + ar0) * K + k0 + ac0);
            cp_async16(&Bs[s2][ar1][ac1], B + (size_t)(bn + ar1) * K + k0 + ac1);
            asm volatile("cp.async.commit_group;\n" ::);
        }

        const int s = kt & 1;
        #pragma unroll
        for (int kk = 0; kk < GBK; kk += 8) {
            uint32_t af[4][4], bf[4][2];
            #pragma unroll
            for (int mt = 0; mt < 4; mt++) {
                const int r = wm + mt * 16 + g;
                af[mt][0] = f2tf(As[s][r][kk + t]);
                af[mt][1] = f2tf(As[s][r + 8][kk + t]);
                af[mt][2] = f2tf(As[s][r][kk + t + 4]);
                af[mt][3] = f2tf(As[s][r + 8][kk + t + 4]);
            }
            #pragma unroll
            for (int nt = 0; nt < 4; nt++) {
                const int cc = wn + nt * 8 + g;
                bf[nt][0] = f2tf(Bs[s][cc][kk + t]);
                bf[nt][1] = f2tf(Bs[s][cc][kk + t + 4]);
            }
            #pragma unroll
            for (int mt = 0; mt < 4; mt++)
                #pragma unroll
                for (int nt = 0; nt < 4; nt++)
                    mma_tf32(c[mt][nt], af[mt], bf[nt]);
        }
    }

    #pragma unroll
    for (int mt = 0; mt < 4; mt++) {
        #pragma unroll
        for (int nt = 0; nt < 4; nt++) {
            const int row = bm + wm + mt * 16 + g;
            const int col = bn + wn + nt * 8 + 2 * t;
            float2 v0 = make_float2(c[mt][nt][0], c[mt][nt][1]);
            float2 v1 = make_float2(c[mt][nt][2], c[mt][nt][3]);
            *(float2*)&C[(size_t)row * N + col]       = v0;
            *(float2*)&C[(size_t)(row + 8) * N + col] = v1;
        }
    }
}

// ---------------------------------------------------------------------------
// Attention: split-bf16 (hi+lo) 3-term MMA flash attention.
// BQ=128, BKV=64, 256 threads (8 warps); warp w owns rows w*16..w*16+15,
// full tile width. QK^T and P@V via mma.m16n8k16 bf16 with fp32 accum:
//   X @ Y ~= Xh@Yh + Xh@Yl + Xl@Yh   (error ~2^-17, preserves logits)
// P fragments rebuilt from S accumulator registers (no smem round-trip).
// ---------------------------------------------------------------------------
#define ABQ  128
#define ABK  64
#define APAD 136   // bf16 row stride (272B: 16B-aligned, ldmatrix conflict-free)
#define ASMEM ((2 * ABQ + 4 * ABK) * APAD * 2)   // 139264 bytes

__device__ __forceinline__ void ldsm_x4(uint32_t r[4], const void* p) {
    uint32_t a = (uint32_t)__cvta_generic_to_shared(p);
    asm volatile("ldmatrix.sync.aligned.m8n8.x4.shared.b16 {%0,%1,%2,%3}, [%4];"
                 : "=r"(r[0]), "=r"(r[1]), "=r"(r[2]), "=r"(r[3]) : "r"(a));
}

__device__ __forceinline__ void ldsm_x4_t(uint32_t r[4], const void* p) {
    uint32_t a = (uint32_t)__cvta_generic_to_shared(p);
    asm volatile("ldmatrix.sync.aligned.m8n8.x4.trans.shared.b16 {%0,%1,%2,%3}, [%4];"
                 : "=r"(r[0]), "=r"(r[1]), "=r"(r[2]), "=r"(r[3]) : "r"(a));
}

__device__ __forceinline__ void mma_bf16(float c[4], const uint32_t a[4],
                                         uint32_t b0, uint32_t b1) {
    asm volatile(
        "mma.sync.aligned.m16n8k16.row.col.f32.bf16.bf16.f32 "
        "{%0,%1,%2,%3},{%4,%5,%6,%7},{%8,%9},{%0,%1,%2,%3};"
        : "+f"(c[0]), "+f"(c[1]), "+f"(c[2]), "+f"(c[3])
        : "r"(a[0]), "r"(a[1]), "r"(a[2]), "r"(a[3]), "r"(b0), "r"(b1));
}

// Split 4 floats into bf16 hi/lo pairs and store (two bf162 stores each).
__device__ __forceinline__ void split_store4(__nv_bfloat16* H, __nv_bfloat16* L,
                                             int off, float4 x) {
    __nv_bfloat162 hA = __floats2bfloat162_rn(x.x, x.y);
    __nv_bfloat162 hB = __floats2bfloat162_rn(x.z, x.w);
    float r0 = x.x - __low2float(hA),  r1 = x.y - __high2float(hA);
    float r2 = x.z - __low2float(hB),  r3 = x.w - __high2float(hB);
    __nv_bfloat162 lA = __floats2bfloat162_rn(r0, r1);
    __nv_bfloat162 lB = __floats2bfloat162_rn(r2, r3);
    *(__nv_bfloat162*)&H[off]     = hA;
    *(__nv_bfloat162*)&H[off + 2] = hB;
    *(__nv_bfloat162*)&L[off]     = lA;
    *(__nv_bfloat162*)&L[off + 2] = lB;
}

__global__ __launch_bounds__(256, 1) void attn_mma(
    const float* __restrict__ Q, const float* __restrict__ Kg,
    const float* __restrict__ Vg, float* __restrict__ Ob,
    const int* __restrict__ n_init_p, const int* __restrict__ n_local_p) {

    extern __shared__ __nv_bfloat16 smb[];
    __nv_bfloat16* Qh = smb;
    __nv_bfloat16* Ql = Qh + ABQ * APAD;
    __nv_bfloat16* Kh = Ql + ABQ * APAD;
    __nv_bfloat16* Kl = Kh + ABK * APAD;
    __nv_bfloat16* Vh = Kl + ABK * APAD;
    __nv_bfloat16* Vl = Vh + ABK * APAD;

    const int h   = blockIdx.y;
    const int q0  = blockIdx.x * ABQ;
    const int hkv = h >> 2;               // NH/NKV = 4
    const int n_init  = *n_init_p;
    const int n_local = *n_local_p;

    const int tid  = threadIdx.x;
    const int warp = tid >> 5;
    const int lane = tid & 31;
    const int g    = lane >> 2;
    const int t    = lane & 3;
    const int grp  = lane >> 3;           // 0..3, for B-matrix ldmatrix addressing

    // ---- stage Q (split hi/lo) ----
    #pragma unroll
    for (int it = 0; it < 16; ++it) {
        int idx = tid + it * 256;                    // 0..4095 float4s
        int r = idx >> 5, c4 = (idx & 31) << 2;
        float4 x = *(const float4*)&Q[(size_t)(q0 + r) * HID + h * HD + c4];
        split_store4(Qh, Ql, r * APAD + c4, x);
    }

    float o[16][4];
    float m_i[2] = {-1e30f, -1e30f};
    float l_i[2] = {0.f, 0.f};
    #pragma unroll
    for (int nb = 0; nb < 16; nb++)
        #pragma unroll
        for (int j = 0; j < 4; j++) o[nb][j] = 0.f;

    const int   row0  = q0 + warp * 16 + g;
    const int   kb_max = (q0 + ABQ - 1) / ABK;
    const float scale  = 0.08838834764831845f;

    for (int kb = 0; kb <= kb_max; ++kb) {
        const int k0 = kb * ABK;
        if (k0 >= n_init && (q0 - (k0 + ABK - 1)) >= n_local) continue;

        __syncthreads();   // previous tile's V reads done before restaging
        // ---- stage K and V tiles (split hi/lo) ----
        #pragma unroll
        for (int it = 0; it < 8; ++it) {
            int idx = tid + it * 256;                // 0..2047 float4s
            int r = idx >> 5, c4 = (idx & 31) << 2;
            float4 xk = *(const float4*)&Kg[(size_t)(k0 + r) * KVDIM + hkv * HD + c4];
            split_store4(Kh, Kl, r * APAD + c4, xk);
            float4 xv = *(const float4*)&Vg[(size_t)(k0 + r) * KVDIM + hkv * HD + c4];
            split_store4(Vh, Vl, r * APAD + c4, xv);
        }
        __syncthreads();

        // ---- S = Q @ K^T (3-term split) ----
        float sc[8][4];
        #pragma unroll
        for (int nb = 0; nb < 8; nb++)
            #pragma unroll
            for (int j = 0; j < 4; j++) sc[nb][j] = 0.f;

        #pragma unroll
        for (int kk = 0; kk < 8; ++kk) {             // d = 128 in k16 steps
            uint32_t qa_h[4], qa_l[4];
            const int aoff = (warp * 16 + (lane & 15)) * APAD + kk * 16 + (lane >> 4) * 8;
            ldsm_x4(qa_h, Qh + aoff);
            ldsm_x4(qa_l, Ql + aoff);
            #pragma unroll
            for (int nbp = 0; nbp < 4; ++nbp) {      // nb pairs (2 per ldmatrix.x4)
                uint32_t kb_h[4], kb_l[4];
                const int boff = (nbp * 16 + (grp >> 1) * 8 + (lane & 7)) * APAD
                               + kk * 16 + (grp & 1) * 8;
                ldsm_x4(kb_h, Kh + boff);
                ldsm_x4(kb_l, Kl + boff);
                mma_bf16(sc[2 * nbp],     qa_h, kb_h[0], kb_h[1]);
                mma_bf16(sc[2 * nbp],     qa_h, kb_l[0], kb_l[1]);
                mma_bf16(sc[2 * nbp],     qa_l, kb_h[0], kb_h[1]);
                mma_bf16(sc[2 * nbp + 1], qa_h, kb_h[2], kb_h[3]);
                mma_bf16(sc[2 * nbp + 1], qa_h, kb_l[2], kb_l[3]);
                mma_bf16(sc[2 * nbp + 1], qa_l, kb_h[2], kb_h[3]);
            }
        }

        // ---- mask + online softmax (rows g and g+8 of this warp) ----
        float tm0 = -1e30f, tm1 = -1e30f;
        #pragma unroll
        for (int nb = 0; nb < 8; ++nb) {
            int cb = k0 + nb * 8 + 2 * t;
            #pragma unroll
            for (int j = 0; j < 2; ++j) {
                int cc = cb + j;
                bool ok0 = (cc <= row0)     && (cc < n_init || row0 - cc < n_local);
                bool ok1 = (cc <= row0 + 8) && (cc < n_init || row0 + 8 - cc < n_local);
                sc[nb][j]     = ok0 ? sc[nb][j] * scale     : -1e30f;
                sc[nb][2 + j] = ok1 ? sc[nb][2 + j] * scale : -1e30f;
                tm0 = fmaxf(tm0, sc[nb][j]);
                tm1 = fmaxf(tm1, sc[nb][2 + j]);
            }
        }
        tm0 = fmaxf(tm0, __shfl_xor_sync(0xffffffffu, tm0, 1));
        tm0 = fmaxf(tm0, __shfl_xor_sync(0xffffffffu, tm0, 2));
        tm1 = fmaxf(tm1, __shfl_xor_sync(0xffffffffu, tm1, 1));
        tm1 = fmaxf(tm1, __shfl_xor_sync(0xffffffffu, tm1, 2));

        float mn0 = fmaxf(m_i[0], tm0), mn1 = fmaxf(m_i[1], tm1);
        float al0 = __expf(m_i[0] - mn0), al1 = __expf(m_i[1] - mn1);
        float rs0 = 0.f, rs1 = 0.f;
        #pragma unroll
        for (int nb = 0; nb < 8; ++nb) {
            #pragma unroll
            for (int j = 0; j < 2; ++j) {
                float p0 = __expf(sc[nb][j] - mn0);
                float p1 = __expf(sc[nb][2 + j] - mn1);
                sc[nb][j] = p0;  sc[nb][2 + j] = p1;
                rs0 += p0;  rs1 += p1;
            }
        }
        rs0 += __shfl_xor_sync(0xffffffffu, rs0, 1);
        rs0 += __shfl_xor_sync(0xffffffffu, rs0, 2);
        rs1 += __shfl_xor_sync(0xffffffffu, rs1, 1);
        rs1 += __shfl_xor_sync(0xffffffffu, rs1, 2);
        l_i[0] = l_i[0] * al0 + rs0;  m_i[0] = mn0;
        l_i[1] = l_i[1] * al1 + rs1;  m_i[1] = mn1;
        #pragma unroll
        for (int nb = 0; nb < 16; ++nb) {
            o[nb][0] *= al0;  o[nb][1] *= al0;
            o[nb][2] *= al1;  o[nb][3] *= al1;
        }

        // ---- pack P fragments (hi/lo) straight from S registers ----
        uint32_t ph[8][2], pl[8][2];
        #pragma unroll
        for (int nb = 0; nb < 8; ++nb) {
            __nv_bfloat162 h0 = __floats2bfloat162_rn(sc[nb][0], sc[nb][1]);
            __nv_bfloat162 h1 = __floats2bfloat162_rn(sc[nb][2], sc[nb][3]);
            float r0 = sc[nb][0] - __low2float(h0), r1 = sc[nb][1] - __high2float(h0);
            float r2 = sc[nb][2] - __low2float(h1), r3 = sc[nb][3] - __high2float(h1);
            __nv_bfloat162 q0b = __floats2bfloat162_rn(r0, r1);
            __nv_bfloat162 q1b = __floats2bfloat162_rn(r2, r3);
            ph[nb][0] = *(uint32_t*)&h0;  ph[nb][1] = *(uint32_t*)&h1;
            pl[nb][0] = *(uint32_t*)&q0b; pl[nb][1] = *(uint32_t*)&q1b;
        }

        // ---- O += P @ V (3-term split); V via ldmatrix.trans ----
        #pragma unroll
        for (int ks = 0; ks < 4; ++ks) {             // key dim 64 in k16 steps
            uint32_t aH[4] = { ph[2 * ks][0], ph[2 * ks][1],
                               ph[2 * ks + 1][0], ph[2 * ks + 1][1] };
            uint32_t aL[4] = { pl[2 * ks][0], pl[2 * ks][1],
                               pl[2 * ks + 1][0], pl[2 * ks + 1][1] };
            #pragma unroll
            for (int np = 0; np < 8; ++np) {         // 16 d-nb in pairs
                uint32_t vh[4], vl[4];
                const int voff = (ks * 16 + (grp & 1) * 8 + (lane & 7)) * APAD
                               + (np * 2 + (grp >> 1)) * 8;
                ldsm_x4_t(vh, Vh + voff);
                ldsm_x4_t(vl, Vl + voff);
                mma_bf16(o[2 * np],     aH, vh[0], vh[1]);
                mma_bf16(o[2 * np],     aH, vl[0], vl[1]);
                mma_bf16(o[2 * np],     aL, vh[0], vh[1]);
                mma_bf16(o[2 * np + 1], aH, vh[2], vh[3]);
                mma_bf16(o[2 * np + 1], aH, vl[2], vl[3]);
                mma_bf16(o[2 * np + 1], aL, vh[2], vh[3]);
            }
        }
    }

    // ---- epilogue ----
    float inv0 = 1.f / l_i[0], inv1 = 1.f / l_i[1];
    #pragma unroll
    for (int nb = 0; nb < 16; ++nb) {
        int col = h * HD + nb * 8 + 2 * t;
        float2 v0 = make_float2(o[nb][0] * inv0, o[nb][1] * inv0);
        float2 v1 = make_float2(o[nb][2] * inv1, o[nb][3] * inv1);
        *(float2*)&Ob[(size_t)row0 * HID + col]       = v0;
        *(float2*)&Ob[(size_t)(row0 + 8) * HID + col] = v1;
    }
}

// ---------------------------------------------------------------------------
extern "C" void kernel_launch(void* const* d_in, const int* in_sizes, int n_in,
                              void* d_out, int out_size) {
    const float* hs = (const float*)d_in[0];
    const float* Wq = (const float*)d_in[1];
    const float* Wk = (const float*)d_in[2];
    const float* Wv = (const float*)d_in[3];
    const float* Wo = (const float*)d_in[4];
    const int* n_init  = (const int*)d_in[5];
    const int* n_local = (const int*)d_in[6];
    float* out = (float*)d_out;

    float *q, *k, *v, *attn;
    cudaGetSymbolAddress((void**)&q,    g_q);
    cudaGetSymbolAddress((void**)&k,    g_k);
    cudaGetSymbolAddress((void**)&v,    g_v);
    cudaGetSymbolAddress((void**)&attn, g_attn);

    static int smem_set = 0;
    if (!smem_set) {
        cudaFuncSetAttribute(attn_mma, cudaFuncAttributeMaxDynamicSharedMemorySize,
                             ASMEM);
        smem_set = 1;
    }

    gemm_tf32<<<dim3(HID / GBN,   S_LEN / GBM), 256>>>(hs, Wq, q, S_LEN, HID,   HID);
    gemm_tf32<<<dim3(KVDIM / GBN, S_LEN / GBM), 256>>>(hs, Wk, k, S_LEN, KVDIM, HID);
    gemm_tf32<<<dim3(KVDIM / GBN, S_LEN / GBM), 256>>>(hs, Wv, v, S_LEN, KVDIM, HID);

    attn_mma<<<dim3(S_LEN / ABQ, NH), 256, ASMEM>>>(q, k, v, attn, n_init, n_local);

    gemm_tf32<<<dim3(HID / GBN, S_LEN / GBM), 256>>>(attn, Wo, out, S_LEN, HID, HID);
}

// round 6
// speedup vs baseline: 3.8767x; 1.3993x over previous
#include <cuda_runtime.h>
#include <cuda_bf16.h>
#include <math.h>
#include <stdint.h>

#define S_LEN 2048
#define HID   4096
#define NH    32
#define NKV   8
#define HD    128
#define KVDIM 1024
#define KDIM  4096
#define KS    (KDIM / 16)   // 256 k-stages

// ---------------- scratch ----------------
__device__ float g_q[S_LEN * HID];
__device__ float g_k[S_LEN * KVDIM];
__device__ float g_v[S_LEN * KVDIM];
__device__ float g_attn[S_LEN * HID];
// fragment-packed tf32 operands (float4 granularity)
__device__ float4 g_pa_hs[(S_LEN / 128) * KS * 512];   // 32 MB
__device__ float4 g_pa_at[(S_LEN / 128) * KS * 512];   // 32 MB
__device__ float4 g_pb_wq[(HID / 128) * KS * 512];     // 64 MB
__device__ float4 g_pb_wk[(KVDIM / 128) * KS * 512];   // 16 MB
__device__ float4 g_pb_wv[(KVDIM / 128) * KS * 512];   // 16 MB
__device__ float4 g_pb_wo[(HID / 128) * KS * 512];     // 64 MB

// ---------------- helpers ----------------
__device__ __forceinline__ uint32_t smem_u32(const void* p) {
    uint32_t a;
    asm("{ .reg .u64 t; cvta.to.shared.u64 t, %1; cvt.u32.u64 %0, t; }" : "=r"(a) : "l"(p));
    return a;
}
__device__ __forceinline__ void cp_async16s(uint32_t s, const void* g) {
    asm volatile("cp.async.cg.shared.global [%0], [%1], 16;\n" :: "r"(s), "l"(g));
}
__device__ __forceinline__ float f2tf_f(float x) {
    uint32_t u;
    asm("cvt.rna.tf32.f32 %0, %1;" : "=r"(u) : "f"(x));
    return __uint_as_float(u);
}
__device__ __forceinline__ void mma_tf32(float c[4], const uint32_t a[4],
                                         uint32_t b0, uint32_t b1) {
    asm volatile(
        "mma.sync.aligned.m16n8k8.row.col.f32.tf32.tf32.f32 "
        "{%0,%1,%2,%3},{%4,%5,%6,%7},{%8,%9},{%0,%1,%2,%3};"
        : "+f"(c[0]), "+f"(c[1]), "+f"(c[2]), "+f"(c[3])
        : "r"(a[0]), "r"(a[1]), "r"(a[2]), "r"(a[3]), "r"(b0), "r"(b1));
}

// ---------------------------------------------------------------------------
// Prepass: pack fp32 matrices into tf32 fragment order.
// A-pack: float4 = (A[r][c], A[r+8][c], A[r][c+4], A[r+8][c+4])
//   index o -> lane(5b) | mb(3b) | kk(1b) | ks(8b) | rb
// B-pack: float4 = (B[n][c], B[n][c+4], B[n+8][c], B[n+8][c+4])
//   index o -> lane(5b) | np(3b) | kk(1b) | ks(8b) | nb
// ---------------------------------------------------------------------------
__global__ void pack_a(const float* __restrict__ X, float4* __restrict__ P, int n) {
    int o = blockIdx.x * 256 + threadIdx.x;
    if (o >= n) return;
    int lane = o & 31, mb = (o >> 5) & 7, kk = (o >> 8) & 1;
    int ks = (o >> 9) & 255, rb = o >> 17;
    int g = lane >> 2, t = lane & 3;
    size_t r0 = (size_t)(rb * 128 + mb * 16 + g);
    int c0 = ks * 16 + kk * 8 + t;
    P[o] = make_float4(f2tf_f(X[r0 * KDIM + c0]),
                       f2tf_f(X[(r0 + 8) * KDIM + c0]),
                       f2tf_f(X[r0 * KDIM + c0 + 4]),
                       f2tf_f(X[(r0 + 8) * KDIM + c0 + 4]));
}

__global__ void pack_b(const float* __restrict__ W, float4* __restrict__ P, int n) {
    int o = blockIdx.x * 256 + threadIdx.x;
    if (o >= n) return;
    int lane = o & 31, np = (o >> 5) & 7, kk = (o >> 8) & 1;
    int ks = (o >> 9) & 255, nb = o >> 17;
    int g = lane >> 2, t = lane & 3;
    size_t c0 = (size_t)(nb * 128 + np * 16 + g);
    int k0 = ks * 16 + kk * 8 + t;
    P[o] = make_float4(f2tf_f(W[c0 * KDIM + k0]),
                       f2tf_f(W[c0 * KDIM + k0 + 4]),
                       f2tf_f(W[(c0 + 8) * KDIM + k0]),
                       f2tf_f(W[(c0 + 8) * KDIM + k0 + 4]));
}

// ---------------------------------------------------------------------------
// Fragment-packed TF32 GEMM: C[M,N] = A @ B^T.
// CTA 128x128, BK=16, 8 warps (2m x 4n), warp tile 64x32.
// Per stage: A 512 f4 (8KB) + B 512 f4 (8KB); 3-stage cp.async ring (48KB).
// Zero in-loop cvt; one LDS.128 per fragment (packed layout).
// ---------------------------------------------------------------------------
#define PK_SMEM 49152

__global__ __launch_bounds__(256, 2)
void gemm_pk(const float4* __restrict__ PA, const float4* __restrict__ PB,
             float* __restrict__ C, int N) {
    extern __shared__ float4 sm4[];   // 3 * 1024 float4
    const int tid = threadIdx.x, warp = tid >> 5, lane = tid & 31;
    const int g = lane >> 2, t = lane & 3;
    const int wmb = (warp & 1) * 4;      // m-block base (16-row units)
    const int wnb = (warp >> 1) * 2;     // np-pair base (16-col units)
    const size_t abase = (size_t)blockIdx.y * KS * 512;
    const size_t bbase = (size_t)blockIdx.x * KS * 512;
    const uint32_t sb = smem_u32(sm4);

    float c[4][4][4];
    #pragma unroll
    for (int mt = 0; mt < 4; mt++)
        #pragma unroll
        for (int nt = 0; nt < 4; nt++)
            #pragma unroll
            for (int i = 0; i < 4; i++) c[mt][nt][i] = 0.f;

    // stage ks into buffer ks%3
    #define STAGE(ks_)                                                          \
        do {                                                                    \
            const uint32_t db = sb + (uint32_t)((ks_) % 3) * 16384u;            \
            _Pragma("unroll")                                                   \
            for (int i_ = 0; i_ < 4; ++i_) {                                    \
                int cix = tid + i_ * 256;                                       \
                const float4* src = (cix < 512)                                 \
                    ? (PA + abase + (size_t)(ks_) * 512 + cix)                  \
                    : (PB + bbase + (size_t)(ks_) * 512 + (cix - 512));         \
                cp_async16s(db + (uint32_t)cix * 16u, src);                     \
            }                                                                   \
            asm volatile("cp.async.commit_group;\n" ::);                        \
        } while (0)

    STAGE(0);
    STAGE(1);

    for (int ks = 0; ks < KS; ++ks) {
        if (ks + 1 < KS) asm volatile("cp.async.wait_group 1;\n" ::);
        else             asm volatile("cp.async.wait_group 0;\n" ::);
        __syncthreads();

        if (ks + 2 < KS) STAGE(ks + 2);

        const float4* As4 = sm4 + (ks % 3) * 1024;
        const float4* Bs4 = As4 + 512;
        #pragma unroll
        for (int kk = 0; kk < 2; ++kk) {
            float4 av[4], bv[2];
            #pragma unroll
            for (int mt = 0; mt < 4; ++mt)
                av[mt] = As4[kk * 256 + (wmb + mt) * 32 + lane];
            #pragma unroll
            for (int np = 0; np < 2; ++np)
                bv[np] = Bs4[kk * 256 + (wnb + np) * 32 + lane];
            #pragma unroll
            for (int mt = 0; mt < 4; ++mt) {
                uint32_t a[4] = { __float_as_uint(av[mt].x), __float_as_uint(av[mt].y),
                                  __float_as_uint(av[mt].z), __float_as_uint(av[mt].w) };
                #pragma unroll
                for (int nt = 0; nt < 4; ++nt) {
                    const float4& b = bv[nt >> 1];
                    uint32_t b0 = (nt & 1) ? __float_as_uint(b.z) : __float_as_uint(b.x);
                    uint32_t b1 = (nt & 1) ? __float_as_uint(b.w) : __float_as_uint(b.y);
                    mma_tf32(c[mt][nt], a, b0, b1);
                }
            }
        }
    }

    const int bm = blockIdx.y * 128, bn = blockIdx.x * 128;
    const int wm = (warp & 1) * 64, wn = (warp >> 1) * 32;
    #pragma unroll
    for (int mt = 0; mt < 4; ++mt) {
        #pragma unroll
        for (int nt = 0; nt < 4; ++nt) {
            const int row = bm + wm + mt * 16 + g;
            const int col = bn + wn + nt * 8 + 2 * t;
            *(float2*)&C[(size_t)row * N + col]       = make_float2(c[mt][nt][0], c[mt][nt][1]);
            *(float2*)&C[(size_t)(row + 8) * N + col] = make_float2(c[mt][nt][2], c[mt][nt][3]);
        }
    }
}

// ---------------------------------------------------------------------------
// Attention (unchanged round-3 split-bf16 mma flash kernel)
// ---------------------------------------------------------------------------
#define ABQ  128
#define ABK  64
#define APAD 136
#define ASMEM ((2 * ABQ + 4 * ABK) * APAD * 2)

__device__ __forceinline__ void ldsm_x4(uint32_t r[4], const void* p) {
    uint32_t a = smem_u32(p);
    asm volatile("ldmatrix.sync.aligned.m8n8.x4.shared.b16 {%0,%1,%2,%3}, [%4];"
                 : "=r"(r[0]), "=r"(r[1]), "=r"(r[2]), "=r"(r[3]) : "r"(a));
}
__device__ __forceinline__ void ldsm_x4_t(uint32_t r[4], const void* p) {
    uint32_t a = smem_u32(p);
    asm volatile("ldmatrix.sync.aligned.m8n8.x4.trans.shared.b16 {%0,%1,%2,%3}, [%4];"
                 : "=r"(r[0]), "=r"(r[1]), "=r"(r[2]), "=r"(r[3]) : "r"(a));
}
__device__ __forceinline__ void mma_bf16(float c[4], const uint32_t a[4],
                                         uint32_t b0, uint32_t b1) {
    asm volatile(
        "mma.sync.aligned.m16n8k16.row.col.f32.bf16.bf16.f32 "
        "{%0,%1,%2,%3},{%4,%5,%6,%7},{%8,%9},{%0,%1,%2,%3};"
        : "+f"(c[0]), "+f"(c[1]), "+f"(c[2]), "+f"(c[3])
        : "r"(a[0]), "r"(a[1]), "r"(a[2]), "r"(a[3]), "r"(b0), "r"(b1));
}
__device__ __forceinline__ void split_store4(__nv_bfloat16* H, __nv_bfloat16* L,
                                             int off, float4 x) {
    __nv_bfloat162 hA = __floats2bfloat162_rn(x.x, x.y);
    __nv_bfloat162 hB = __floats2bfloat162_rn(x.z, x.w);
    *(__nv_bfloat162*)&H[off]     = hA;
    *(__nv_bfloat162*)&H[off + 2] = hB;
    *(__nv_bfloat162*)&L[off]     = __floats2bfloat162_rn(x.x - __low2float(hA), x.y - __high2float(hA));
    *(__nv_bfloat162*)&L[off + 2] = __floats2bfloat162_rn(x.z - __low2float(hB), x.w - __high2float(hB));
}

__global__ __launch_bounds__(256, 1) void attn_mma(
    const float* __restrict__ Q, const float* __restrict__ Kg,
    const float* __restrict__ Vg, float* __restrict__ Ob,
    const int* __restrict__ n_init_p, const int* __restrict__ n_local_p) {

    extern __shared__ __nv_bfloat16 smb[];
    __nv_bfloat16* Qh = smb;
    __nv_bfloat16* Ql = Qh + ABQ * APAD;
    __nv_bfloat16* Kh = Ql + ABQ * APAD;
    __nv_bfloat16* Kl = Kh + ABK * APAD;
    __nv_bfloat16* Vh = Kl + ABK * APAD;
    __nv_bfloat16* Vl = Vh + ABK * APAD;

    const int h   = blockIdx.y;
    const int q0  = blockIdx.x * ABQ;
    const int hkv = h >> 2;
    const int n_init  = *n_init_p;
    const int n_local = *n_local_p;

    const int tid  = threadIdx.x;
    const int warp = tid >> 5;
    const int lane = tid & 31;
    const int g    = lane >> 2;
    const int t    = lane & 3;
    const int grp  = lane >> 3;

    #pragma unroll
    for (int it = 0; it < 16; ++it) {
        int idx = tid + it * 256;
        int r = idx >> 5, c4 = (idx & 31) << 2;
        float4 x = *(const float4*)&Q[(size_t)(q0 + r) * HID + h * HD + c4];
        split_store4(Qh, Ql, r * APAD + c4, x);
    }

    float o[16][4];
    float m_i[2] = {-1e30f, -1e30f};
    float l_i[2] = {0.f, 0.f};
    #pragma unroll
    for (int nb = 0; nb < 16; nb++)
        #pragma unroll
        for (int j = 0; j < 4; j++) o[nb][j] = 0.f;

    const int   row0   = q0 + warp * 16 + g;
    const int   kb_max = (q0 + ABQ - 1) / ABK;
    const float scale  = 0.08838834764831845f;

    for (int kb = 0; kb <= kb_max; ++kb) {
        const int k0 = kb * ABK;
        if (k0 >= n_init && (q0 - (k0 + ABK - 1)) >= n_local) continue;

        __syncthreads();
        #pragma unroll
        for (int it = 0; it < 8; ++it) {
            int idx = tid + it * 256;
            int r = idx >> 5, c4 = (idx & 31) << 2;
            float4 xk = *(const float4*)&Kg[(size_t)(k0 + r) * KVDIM + hkv * HD + c4];
            split_store4(Kh, Kl, r * APAD + c4, xk);
            float4 xv = *(const float4*)&Vg[(size_t)(k0 + r) * KVDIM + hkv * HD + c4];
            split_store4(Vh, Vl, r * APAD + c4, xv);
        }
        __syncthreads();

        float sc[8][4];
        #pragma unroll
        for (int nb = 0; nb < 8; nb++)
            #pragma unroll
            for (int j = 0; j < 4; j++) sc[nb][j] = 0.f;

        #pragma unroll
        for (int kk = 0; kk < 8; ++kk) {
            uint32_t qa_h[4], qa_l[4];
            const int aoff = (warp * 16 + (lane & 15)) * APAD + kk * 16 + (lane >> 4) * 8;
            ldsm_x4(qa_h, Qh + aoff);
            ldsm_x4(qa_l, Ql + aoff);
            #pragma unroll
            for (int nbp = 0; nbp < 4; ++nbp) {
                uint32_t kb_h[4], kb_l[4];
                const int boff = (nbp * 16 + (grp >> 1) * 8 + (lane & 7)) * APAD
                               + kk * 16 + (grp & 1) * 8;
                ldsm_x4(kb_h, Kh + boff);
                ldsm_x4(kb_l, Kl + boff);
                mma_bf16(sc[2 * nbp],     qa_h, kb_h[0], kb_h[1]);
                mma_bf16(sc[2 * nbp],     qa_h, kb_l[0], kb_l[1]);
                mma_bf16(sc[2 * nbp],     qa_l, kb_h[0], kb_h[1]);
                mma_bf16(sc[2 * nbp + 1], qa_h, kb_h[2], kb_h[3]);
                mma_bf16(sc[2 * nbp + 1], qa_h, kb_l[2], kb_l[3]);
                mma_bf16(sc[2 * nbp + 1], qa_l, kb_h[2], kb_h[3]);
            }
        }

        float tm0 = -1e30f, tm1 = -1e30f;
        #pragma unroll
        for (int nb = 0; nb < 8; ++nb) {
            int cb = k0 + nb * 8 + 2 * t;
            #pragma unroll
            for (int j = 0; j < 2; ++j) {
                int cc = cb + j;
                bool ok0 = (cc <= row0)     && (cc < n_init || row0 - cc < n_local);
                bool ok1 = (cc <= row0 + 8) && (cc < n_init || row0 + 8 - cc < n_local);
                sc[nb][j]     = ok0 ? sc[nb][j] * scale     : -1e30f;
                sc[nb][2 + j] = ok1 ? sc[nb][2 + j] * scale : -1e30f;
                tm0 = fmaxf(tm0, sc[nb][j]);
                tm1 = fmaxf(tm1, sc[nb][2 + j]);
            }
        }
        tm0 = fmaxf(tm0, __shfl_xor_sync(0xffffffffu, tm0, 1));
        tm0 = fmaxf(tm0, __shfl_xor_sync(0xffffffffu, tm0, 2));
        tm1 = fmaxf(tm1, __shfl_xor_sync(0xffffffffu, tm1, 1));
        tm1 = fmaxf(tm1, __shfl_xor_sync(0xffffffffu, tm1, 2));

        float mn0 = fmaxf(m_i[0], tm0), mn1 = fmaxf(m_i[1], tm1);
        float al0 = __expf(m_i[0] - mn0), al1 = __expf(m_i[1] - mn1);
        float rs0 = 0.f, rs1 = 0.f;
        #pragma unroll
        for (int nb = 0; nb < 8; ++nb) {
            #pragma unroll
            for (int j = 0; j < 2; ++j) {
                float p0 = __expf(sc[nb][j] - mn0);
                float p1 = __expf(sc[nb][2 + j] - mn1);
                sc[nb][j] = p0;  sc[nb][2 + j] = p1;
                rs0 += p0;  rs1 += p1;
            }
        }
        rs0 += __shfl_xor_sync(0xffffffffu, rs0, 1);
        rs0 += __shfl_xor_sync(0xffffffffu, rs0, 2);
        rs1 += __shfl_xor_sync(0xffffffffu, rs1, 1);
        rs1 += __shfl_xor_sync(0xffffffffu, rs1, 2);
        l_i[0] = l_i[0] * al0 + rs0;  m_i[0] = mn0;
        l_i[1] = l_i[1] * al1 + rs1;  m_i[1] = mn1;
        #pragma unroll
        for (int nb = 0; nb < 16; ++nb) {
            o[nb][0] *= al0;  o[nb][1] *= al0;
            o[nb][2] *= al1;  o[nb][3] *= al1;
        }

        uint32_t ph[8][2], pl[8][2];
        #pragma unroll
        for (int nb = 0; nb < 8; ++nb) {
            __nv_bfloat162 h0 = __floats2bfloat162_rn(sc[nb][0], sc[nb][1]);
            __nv_bfloat162 h1 = __floats2bfloat162_rn(sc[nb][2], sc[nb][3]);
            float r0 = sc[nb][0] - __low2float(h0), r1 = sc[nb][1] - __high2float(h0);
            float r2 = sc[nb][2] - __low2float(h1), r3 = sc[nb][3] - __high2float(h1);
            __nv_bfloat162 q0b = __floats2bfloat162_rn(r0, r1);
            __nv_bfloat162 q1b = __floats2bfloat162_rn(r2, r3);
            ph[nb][0] = *(uint32_t*)&h0;  ph[nb][1] = *(uint32_t*)&h1;
            pl[nb][0] = *(uint32_t*)&q0b; pl[nb][1] = *(uint32_t*)&q1b;
        }

        #pragma unroll
        for (int ks = 0; ks < 4; ++ks) {
            uint32_t aH[4] = { ph[2 * ks][0], ph[2 * ks][1],
                               ph[2 * ks + 1][0], ph[2 * ks + 1][1] };
            uint32_t aL[4] = { pl[2 * ks][0], pl[2 * ks][1],
                               pl[2 * ks + 1][0], pl[2 * ks + 1][1] };
            #pragma unroll
            for (int np = 0; np < 8; ++np) {
                uint32_t vh[4], vl[4];
                const int voff = (ks * 16 + (grp & 1) * 8 + (lane & 7)) * APAD
                               + (np * 2 + (grp >> 1)) * 8;
                ldsm_x4_t(vh, Vh + voff);
                ldsm_x4_t(vl, Vl + voff);
                mma_bf16(o[2 * np],     aH, vh[0], vh[1]);
                mma_bf16(o[2 * np],     aH, vl[0], vl[1]);
                mma_bf16(o[2 * np],     aL, vh[0], vh[1]);
                mma_bf16(o[2 * np + 1], aH, vh[2], vh[3]);
                mma_bf16(o[2 * np + 1], aH, vl[2], vl[3]);
                mma_bf16(o[2 * np + 1], aL, vh[2], vh[3]);
            }
        }
    }

    float inv0 = 1.f / l_i[0], inv1 = 1.f / l_i[1];
    #pragma unroll
    for (int nb = 0; nb < 16; ++nb) {
        int col = h * HD + nb * 8 + 2 * t;
        *(float2*)&Ob[(size_t)row0 * HID + col]       = make_float2(o[nb][0] * inv0, o[nb][1] * inv0);
        *(float2*)&Ob[(size_t)(row0 + 8) * HID + col] = make_float2(o[nb][2] * inv1, o[nb][3] * inv1);
    }
}

// ---------------------------------------------------------------------------
extern "C" void kernel_launch(void* const* d_in, const int* in_sizes, int n_in,
                              void* d_out, int out_size) {
    const float* hs = (const float*)d_in[0];
    const float* Wq = (const float*)d_in[1];
    const float* Wk = (const float*)d_in[2];
    const float* Wv = (const float*)d_in[3];
    const float* Wo = (const float*)d_in[4];
    const int* n_init  = (const int*)d_in[5];
    const int* n_local = (const int*)d_in[6];
    float* out = (float*)d_out;

    float *q, *k, *v, *attn;
    cudaGetSymbolAddress((void**)&q,    g_q);
    cudaGetSymbolAddress((void**)&k,    g_k);
    cudaGetSymbolAddress((void**)&v,    g_v);
    cudaGetSymbolAddress((void**)&attn, g_attn);
    float4 *pa_hs, *pa_at, *pb_wq, *pb_wk, *pb_wv, *pb_wo;
    cudaGetSymbolAddress((void**)&pa_hs, g_pa_hs);
    cudaGetSymbolAddress((void**)&pa_at, g_pa_at);
    cudaGetSymbolAddress((void**)&pb_wq, g_pb_wq);
    cudaGetSymbolAddress((void**)&pb_wk, g_pb_wk);
    cudaGetSymbolAddress((void**)&pb_wv, g_pb_wv);
    cudaGetSymbolAddress((void**)&pb_wo, g_pb_wo);

    static int attr_set = 0;
    if (!attr_set) {
        cudaFuncSetAttribute(attn_mma, cudaFuncAttributeMaxDynamicSharedMemorySize, ASMEM);
        attr_set = 1;
    }

    const int na_hs = (S_LEN / 128) * KS * 512;     // 2,097,152
    const int nb_wq = (HID / 128) * KS * 512;       // 4,194,304
    const int nb_wk = (KVDIM / 128) * KS * 512;     // 1,048,576

    // prepass: tf32-round + fragment-pack
    pack_a<<<na_hs / 256, 256>>>(hs, pa_hs, na_hs);
    pack_b<<<nb_wq / 256, 256>>>(Wq, pb_wq, nb_wq);
    pack_b<<<nb_wk / 256, 256>>>(Wk, pb_wk, nb_wk);
    pack_b<<<nb_wk / 256, 256>>>(Wv, pb_wv, nb_wk);
    pack_b<<<nb_wq / 256, 256>>>(Wo, pb_wo, nb_wq);

    // projections
    gemm_pk<<<dim3(HID / 128,   S_LEN / 128), 256, PK_SMEM>>>(pa_hs, pb_wq, q, HID);
    gemm_pk<<<dim3(KVDIM / 128, S_LEN / 128), 256, PK_SMEM>>>(pa_hs, pb_wk, k, KVDIM);
    gemm_pk<<<dim3(KVDIM / 128, S_LEN / 128), 256, PK_SMEM>>>(pa_hs, pb_wv, v, KVDIM);

    attn_mma<<<dim3(S_LEN / ABQ, NH), 256, ASMEM>>>(q, k, v, attn, n_init, n_local);

    pack_a<<<na_hs / 256, 256>>>(attn, pa_at, na_hs);
    gemm_pk<<<dim3(HID / 128, S_LEN / 128), 256, PK_SMEM>>>(pa_at, pb_wo, out, HID);
}

// round 7
// speedup vs baseline: 4.1165x; 1.0619x over previous
#include <cuda_runtime.h>
#include <cuda_bf16.h>
#include <math.h>
#include <stdint.h>

#define S_LEN 2048
#define HID   4096
#define NH    32
#define NKV   8
#define HD    128
#define KVDIM 1024
#define KDIM  4096
#define KS    (KDIM / 16)   // 256 k16 units
#define KS2   (KDIM / 32)   // 128 k32 stages

// ---------------- scratch ----------------
__device__ float g_q[S_LEN * HID];
__device__ float g_k[S_LEN * KVDIM];
__device__ float g_v[S_LEN * KVDIM];
__device__ float g_attn[S_LEN * HID];
__device__ float4 g_pa_hs[(S_LEN / 128) * KS * 512];
__device__ float4 g_pa_at[(S_LEN / 128) * KS * 512];
__device__ float4 g_pb_wq[(HID / 128) * KS * 512];
__device__ float4 g_pb_wk[(KVDIM / 128) * KS * 512];
__device__ float4 g_pb_wv[(KVDIM / 128) * KS * 512];
__device__ float4 g_pb_wo[(HID / 128) * KS * 512];

// ---------------- helpers ----------------
__device__ __forceinline__ uint32_t smem_u32(const void* p) {
    uint32_t a;
    asm("{ .reg .u64 t; cvta.to.shared.u64 t, %1; cvt.u32.u64 %0, t; }" : "=r"(a) : "l"(p));
    return a;
}
__device__ __forceinline__ void cp_async16s(uint32_t s, const void* g) {
    asm volatile("cp.async.cg.shared.global [%0], [%1], 16;\n" :: "r"(s), "l"(g));
}
__device__ __forceinline__ float f2tf_f(float x) {
    uint32_t u;
    asm("cvt.rna.tf32.f32 %0, %1;" : "=r"(u) : "f"(x));
    return __uint_as_float(u);
}
__device__ __forceinline__ void mma_tf32(float c[4], const uint32_t a[4],
                                         uint32_t b0, uint32_t b1) {
    asm volatile(
        "mma.sync.aligned.m16n8k8.row.col.f32.tf32.tf32.f32 "
        "{%0,%1,%2,%3},{%4,%5,%6,%7},{%8,%9},{%0,%1,%2,%3};"
        : "+f"(c[0]), "+f"(c[1]), "+f"(c[2]), "+f"(c[3])
        : "r"(a[0]), "r"(a[1]), "r"(a[2]), "r"(a[3]), "r"(b0), "r"(b1));
}

// ---------------------------------------------------------------------------
// Prepass: tf32-round + fragment-pack (unchanged layout from round 6)
// ---------------------------------------------------------------------------
__global__ void pack_a(const float* __restrict__ X, float4* __restrict__ P, int n) {
    int o = blockIdx.x * 256 + threadIdx.x;
    if (o >= n) return;
    int lane = o & 31, mb = (o >> 5) & 7, kk = (o >> 8) & 1;
    int ks = (o >> 9) & 255, rb = o >> 17;
    int g = lane >> 2, t = lane & 3;
    size_t r0 = (size_t)(rb * 128 + mb * 16 + g);
    int c0 = ks * 16 + kk * 8 + t;
    P[o] = make_float4(f2tf_f(X[r0 * KDIM + c0]),
                       f2tf_f(X[(r0 + 8) * KDIM + c0]),
                       f2tf_f(X[r0 * KDIM + c0 + 4]),
                       f2tf_f(X[(r0 + 8) * KDIM + c0 + 4]));
}

__global__ void pack_b(const float* __restrict__ W, float4* __restrict__ P, int n) {
    int o = blockIdx.x * 256 + threadIdx.x;
    if (o >= n) return;
    int lane = o & 31, np = (o >> 5) & 7, kk = (o >> 8) & 1;
    int ks = (o >> 9) & 255, nb = o >> 17;
    int g = lane >> 2, t = lane & 3;
    size_t c0 = (size_t)(nb * 128 + np * 16 + g);
    int k0 = ks * 16 + kk * 8 + t;
    P[o] = make_float4(f2tf_f(W[c0 * KDIM + k0]),
                       f2tf_f(W[c0 * KDIM + k0 + 4]),
                       f2tf_f(W[(c0 + 8) * KDIM + k0]),
                       f2tf_f(W[(c0 + 8) * KDIM + k0 + 4]));
}

// ---------------------------------------------------------------------------
// Fragment-packed TF32 GEMM v2: CTA 128x256, 8 warps (2m x 4n), warp 64x64.
// k=32 per stage (two k16 units), 3-stage cp.async ring (144 KB smem).
// Per warp-stage: 12 cp.async + 32 LDS.128 + 128 HMMA.
// ---------------------------------------------------------------------------
#define STG_F4  3072                    // f4 per stage: A 1024 + B 2048
#define STG_BY  (STG_F4 * 16)           // 49152 bytes
#define PK2_SMEM (3 * STG_BY)           // 147456

__global__ __launch_bounds__(256, 1)
void gemm_pk2(const float4* __restrict__ PA,
              const float4* __restrict__ B0, int nt0, float* C0, int ld0,
              const float4* __restrict__ B1, int nt1, float* C1, int ld1,
              const float4* __restrict__ B2, int nt2, float* C2, int ld2) {
    extern __shared__ float4 sm4[];
    const int tid = threadIdx.x, warp = tid >> 5, lane = tid & 31;
    const int g = lane >> 2, t = lane & 3;
    const int wm = warp & 1;          // m half (64 rows)
    const int wn = warp >> 1;         // n quarter (64 cols)
    const uint32_t sb = smem_u32(sm4);

    // select output segment by blockIdx.x
    int nt = blockIdx.x;
    const float4* PB;  float* C;  int ld;
    if (nt < nt0)            { PB = B0; C = C0; ld = ld0; }
    else if (nt < nt0 + nt1) { nt -= nt0;       PB = B1; C = C1; ld = ld1; }
    else                     { nt -= nt0 + nt1; PB = B2; C = C2; ld = ld2; }

    const size_t abase  = (size_t)blockIdx.y * KS * 512;
    const size_t bbase0 = (size_t)(2 * nt)     * KS * 512;
    const size_t bbase1 = (size_t)(2 * nt + 1) * KS * 512;

    float c[4][8][4];
    #pragma unroll
    for (int mt = 0; mt < 4; mt++)
        #pragma unroll
        for (int ntb = 0; ntb < 8; ntb++)
            #pragma unroll
            for (int i = 0; i < 4; i++) c[mt][ntb][i] = 0.f;

    // stage s (k32) into buffer s%3
    #define STAGE2(s_)                                                          \
        do {                                                                    \
            const uint32_t db = sb + (uint32_t)((s_) % 3) * STG_BY;             \
            const size_t koff = (size_t)(s_) * 1024;                            \
            _Pragma("unroll")                                                   \
            for (int i_ = 0; i_ < 12; ++i_) {                                   \
                int cix = tid + i_ * 256;                                       \
                const float4* src;                                              \
                if (cix < 1024)       src = PA + abase  + koff + cix;           \
                else if (cix < 2048)  src = PB + bbase0 + koff + (cix - 1024);  \
                else                  src = PB + bbase1 + koff + (cix - 2048);  \
                cp_async16s(db + (uint32_t)cix * 16u, src);                     \
            }                                                                   \
            asm volatile("cp.async.commit_group;\n" ::);                        \
        } while (0)

    STAGE2(0);
    STAGE2(1);

    const int bblk = wn >> 1;             // which 128-col B block
    const int bnp0 = (wn & 1) * 4;        // np base within block

    for (int s = 0; s < KS2; ++s) {
        if (s + 1 < KS2) asm volatile("cp.async.wait_group 1;\n" ::);
        else             asm volatile("cp.async.wait_group 0;\n" ::);
        __syncthreads();

        if (s + 2 < KS2) STAGE2(s + 2);

        const float4* As4 = sm4 + (s % 3) * STG_F4;
        const float4* Bs4 = As4 + 1024 + bblk * 1024;
        #pragma unroll
        for (int kk2 = 0; kk2 < 4; ++kk2) {   // 4 x k8
            const int koffs = (kk2 >> 1) * 512 + (kk2 & 1) * 256;
            float4 av[4], bv[4];
            #pragma unroll
            for (int mt = 0; mt < 4; ++mt)
                av[mt] = As4[koffs + (wm * 4 + mt) * 32 + lane];
            #pragma unroll
            for (int np = 0; np < 4; ++np)
                bv[np] = Bs4[koffs + (bnp0 + np) * 32 + lane];
            #pragma unroll
            for (int mt = 0; mt < 4; ++mt) {
                uint32_t a[4] = { __float_as_uint(av[mt].x), __float_as_uint(av[mt].y),
                                  __float_as_uint(av[mt].z), __float_as_uint(av[mt].w) };
                #pragma unroll
                for (int ntb = 0; ntb < 8; ++ntb) {
                    const float4& b = bv[ntb >> 1];
                    uint32_t b0 = (ntb & 1) ? __float_as_uint(b.z) : __float_as_uint(b.x);
                    uint32_t b1 = (ntb & 1) ? __float_as_uint(b.w) : __float_as_uint(b.y);
                    mma_tf32(c[mt][ntb], a, b0, b1);
                }
            }
        }
    }

    const int bm = blockIdx.y * 128, bn = nt * 256;
    #pragma unroll
    for (int mt = 0; mt < 4; ++mt) {
        #pragma unroll
        for (int ntb = 0; ntb < 8; ++ntb) {
            const int row = bm + wm * 64 + mt * 16 + g;
            const int col = bn + wn * 64 + ntb * 8 + 2 * t;
            *(float2*)&C[(size_t)row * ld + col]       = make_float2(c[mt][ntb][0], c[mt][ntb][1]);
            *(float2*)&C[(size_t)(row + 8) * ld + col] = make_float2(c[mt][ntb][2], c[mt][ntb][3]);
        }
    }
}

// ---------------------------------------------------------------------------
// Attention (unchanged round-3 split-bf16 mma flash kernel)
// ---------------------------------------------------------------------------
#define ABQ  128
#define ABK  64
#define APAD 136
#define ASMEM ((2 * ABQ + 4 * ABK) * APAD * 2)

__device__ __forceinline__ void ldsm_x4(uint32_t r[4], const void* p) {
    uint32_t a = smem_u32(p);
    asm volatile("ldmatrix.sync.aligned.m8n8.x4.shared.b16 {%0,%1,%2,%3}, [%4];"
                 : "=r"(r[0]), "=r"(r[1]), "=r"(r[2]), "=r"(r[3]) : "r"(a));
}
__device__ __forceinline__ void ldsm_x4_t(uint32_t r[4], const void* p) {
    uint32_t a = smem_u32(p);
    asm volatile("ldmatrix.sync.aligned.m8n8.x4.trans.shared.b16 {%0,%1,%2,%3}, [%4];"
                 : "=r"(r[0]), "=r"(r[1]), "=r"(r[2]), "=r"(r[3]) : "r"(a));
}
__device__ __forceinline__ void mma_bf16(float c[4], const uint32_t a[4],
                                         uint32_t b0, uint32_t b1) {
    asm volatile(
        "mma.sync.aligned.m16n8k16.row.col.f32.bf16.bf16.f32 "
        "{%0,%1,%2,%3},{%4,%5,%6,%7},{%8,%9},{%0,%1,%2,%3};"
        : "+f"(c[0]), "+f"(c[1]), "+f"(c[2]), "+f"(c[3])
        : "r"(a[0]), "r"(a[1]), "r"(a[2]), "r"(a[3]), "r"(b0), "r"(b1));
}
__device__ __forceinline__ void split_store4(__nv_bfloat16* H, __nv_bfloat16* L,
                                             int off, float4 x) {
    __nv_bfloat162 hA = __floats2bfloat162_rn(x.x, x.y);
    __nv_bfloat162 hB = __floats2bfloat162_rn(x.z, x.w);
    *(__nv_bfloat162*)&H[off]     = hA;
    *(__nv_bfloat162*)&H[off + 2] = hB;
    *(__nv_bfloat162*)&L[off]     = __floats2bfloat162_rn(x.x - __low2float(hA), x.y - __high2float(hA));
    *(__nv_bfloat162*)&L[off + 2] = __floats2bfloat162_rn(x.z - __low2float(hB), x.w - __high2float(hB));
}

__global__ __launch_bounds__(256, 1) void attn_mma(
    const float* __restrict__ Q, const float* __restrict__ Kg,
    const float* __restrict__ Vg, float* __restrict__ Ob,
    const int* __restrict__ n_init_p, const int* __restrict__ n_local_p) {

    extern __shared__ __nv_bfloat16 smb[];
    __nv_bfloat16* Qh = smb;
    __nv_bfloat16* Ql = Qh + ABQ * APAD;
    __nv_bfloat16* Kh = Ql + ABQ * APAD;
    __nv_bfloat16* Kl = Kh + ABK * APAD;
    __nv_bfloat16* Vh = Kl + ABK * APAD;
    __nv_bfloat16* Vl = Vh + ABK * APAD;

    const int h   = blockIdx.y;
    const int q0  = blockIdx.x * ABQ;
    const int hkv = h >> 2;
    const int n_init  = *n_init_p;
    const int n_local = *n_local_p;

    const int tid  = threadIdx.x;
    const int warp = tid >> 5;
    const int lane = tid & 31;
    const int g    = lane >> 2;
    const int t    = lane & 3;
    const int grp  = lane >> 3;

    #pragma unroll
    for (int it = 0; it < 16; ++it) {
        int idx = tid + it * 256;
        int r = idx >> 5, c4 = (idx & 31) << 2;
        float4 x = *(const float4*)&Q[(size_t)(q0 + r) * HID + h * HD + c4];
        split_store4(Qh, Ql, r * APAD + c4, x);
    }

    float o[16][4];
    float m_i[2] = {-1e30f, -1e30f};
    float l_i[2] = {0.f, 0.f};
    #pragma unroll
    for (int nb = 0; nb < 16; nb++)
        #pragma unroll
        for (int j = 0; j < 4; j++) o[nb][j] = 0.f;

    const int   row0   = q0 + warp * 16 + g;
    const int   kb_max = (q0 + ABQ - 1) / ABK;
    const float scale  = 0.08838834764831845f;

    for (int kb = 0; kb <= kb_max; ++kb) {
        const int k0 = kb * ABK;
        if (k0 >= n_init && (q0 - (k0 + ABK - 1)) >= n_local) continue;

        __syncthreads();
        #pragma unroll
        for (int it = 0; it < 8; ++it) {
            int idx = tid + it * 256;
            int r = idx >> 5, c4 = (idx & 31) << 2;
            float4 xk = *(const float4*)&Kg[(size_t)(k0 + r) * KVDIM + hkv * HD + c4];
            split_store4(Kh, Kl, r * APAD + c4, xk);
            float4 xv = *(const float4*)&Vg[(size_t)(k0 + r) * KVDIM + hkv * HD + c4];
            split_store4(Vh, Vl, r * APAD + c4, xv);
        }
        __syncthreads();

        float sc[8][4];
        #pragma unroll
        for (int nb = 0; nb < 8; nb++)
            #pragma unroll
            for (int j = 0; j < 4; j++) sc[nb][j] = 0.f;

        #pragma unroll
        for (int kk = 0; kk < 8; ++kk) {
            uint32_t qa_h[4], qa_l[4];
            const int aoff = (warp * 16 + (lane & 15)) * APAD + kk * 16 + (lane >> 4) * 8;
            ldsm_x4(qa_h, Qh + aoff);
            ldsm_x4(qa_l, Ql + aoff);
            #pragma unroll
            for (int nbp = 0; nbp < 4; ++nbp) {
                uint32_t kb_h[4], kb_l[4];
                const int boff = (nbp * 16 + (grp >> 1) * 8 + (lane & 7)) * APAD
                               + kk * 16 + (grp & 1) * 8;
                ldsm_x4(kb_h, Kh + boff);
                ldsm_x4(kb_l, Kl + boff);
                mma_bf16(sc[2 * nbp],     qa_h, kb_h[0], kb_h[1]);
                mma_bf16(sc[2 * nbp],     qa_h, kb_l[0], kb_l[1]);
                mma_bf16(sc[2 * nbp],     qa_l, kb_h[0], kb_h[1]);
                mma_bf16(sc[2 * nbp + 1], qa_h, kb_h[2], kb_h[3]);
                mma_bf16(sc[2 * nbp + 1], qa_h, kb_l[2], kb_l[3]);
                mma_bf16(sc[2 * nbp + 1], qa_l, kb_h[2], kb_h[3]);
            }
        }

        float tm0 = -1e30f, tm1 = -1e30f;
        #pragma unroll
        for (int nb = 0; nb < 8; ++nb) {
            int cb = k0 + nb * 8 + 2 * t;
            #pragma unroll
            for (int j = 0; j < 2; ++j) {
                int cc = cb + j;
                bool ok0 = (cc <= row0)     && (cc < n_init || row0 - cc < n_local);
                bool ok1 = (cc <= row0 + 8) && (cc < n_init || row0 + 8 - cc < n_local);
                sc[nb][j]     = ok0 ? sc[nb][j] * scale     : -1e30f;
                sc[nb][2 + j] = ok1 ? sc[nb][2 + j] * scale : -1e30f;
                tm0 = fmaxf(tm0, sc[nb][j]);
                tm1 = fmaxf(tm1, sc[nb][2 + j]);
            }
        }
        tm0 = fmaxf(tm0, __shfl_xor_sync(0xffffffffu, tm0, 1));
        tm0 = fmaxf(tm0, __shfl_xor_sync(0xffffffffu, tm0, 2));
        tm1 = fmaxf(tm1, __shfl_xor_sync(0xffffffffu, tm1, 1));
        tm1 = fmaxf(tm1, __shfl_xor_sync(0xffffffffu, tm1, 2));

        float mn0 = fmaxf(m_i[0], tm0), mn1 = fmaxf(m_i[1], tm1);
        float al0 = __expf(m_i[0] - mn0), al1 = __expf(m_i[1] - mn1);
        float rs0 = 0.f, rs1 = 0.f;
        #pragma unroll
        for (int nb = 0; nb < 8; ++nb) {
            #pragma unroll
            for (int j = 0; j < 2; ++j) {
                float p0 = __expf(sc[nb][j] - mn0);
                float p1 = __expf(sc[nb][2 + j] - mn1);
                sc[nb][j] = p0;  sc[nb][2 + j] = p1;
                rs0 += p0;  rs1 += p1;
            }
        }
        rs0 += __shfl_xor_sync(0xffffffffu, rs0, 1);
        rs0 += __shfl_xor_sync(0xffffffffu, rs0, 2);
        rs1 += __shfl_xor_sync(0xffffffffu, rs1, 1);
        rs1 += __shfl_xor_sync(0xffffffffu, rs1, 2);
        l_i[0] = l_i[0] * al0 + rs0;  m_i[0] = mn0;
        l_i[1] = l_i[1] * al1 + rs1;  m_i[1] = mn1;
        #pragma unroll
        for (int nb = 0; nb < 16; ++nb) {
            o[nb][0] *= al0;  o[nb][1] *= al0;
            o[nb][2] *= al1;  o[nb][3] *= al1;
        }

        uint32_t ph[8][2], pl[8][2];
        #pragma unroll
        for (int nb = 0; nb < 8; ++nb) {
            __nv_bfloat162 h0 = __floats2bfloat162_rn(sc[nb][0], sc[nb][1]);
            __nv_bfloat162 h1 = __floats2bfloat162_rn(sc[nb][2], sc[nb][3]);
            float r0 = sc[nb][0] - __low2float(h0), r1 = sc[nb][1] - __high2float(h0);
            float r2 = sc[nb][2] - __low2float(h1), r3 = sc[nb][3] - __high2float(h1);
            __nv_bfloat162 q0b = __floats2bfloat162_rn(r0, r1);
            __nv_bfloat162 q1b = __floats2bfloat162_rn(r2, r3);
            ph[nb][0] = *(uint32_t*)&h0;  ph[nb][1] = *(uint32_t*)&h1;
            pl[nb][0] = *(uint32_t*)&q0b; pl[nb][1] = *(uint32_t*)&q1b;
        }

        #pragma unroll
        for (int ks = 0; ks < 4; ++ks) {
            uint32_t aH[4] = { ph[2 * ks][0], ph[2 * ks][1],
                               ph[2 * ks + 1][0], ph[2 * ks + 1][1] };
            uint32_t aL[4] = { pl[2 * ks][0], pl[2 * ks][1],
                               pl[2 * ks + 1][0], pl[2 * ks + 1][1] };
            #pragma unroll
            for (int np = 0; np < 8; ++np) {
                uint32_t vh[4], vl[4];
                const int voff = (ks * 16 + (grp & 1) * 8 + (lane & 7)) * APAD
                               + (np * 2 + (grp >> 1)) * 8;
                ldsm_x4_t(vh, Vh + voff);
                ldsm_x4_t(vl, Vl + voff);
                mma_bf16(o[2 * np],     aH, vh[0], vh[1]);
                mma_bf16(o[2 * np],     aH, vl[0], vl[1]);
                mma_bf16(o[2 * np],     aL, vh[0], vh[1]);
                mma_bf16(o[2 * np + 1], aH, vh[2], vh[3]);
                mma_bf16(o[2 * np + 1], aH, vl[2], vl[3]);
                mma_bf16(o[2 * np + 1], aL, vh[2], vh[3]);
            }
        }
    }

    float inv0 = 1.f / l_i[0], inv1 = 1.f / l_i[1];
    #pragma unroll
    for (int nb = 0; nb < 16; ++nb) {
        int col = h * HD + nb * 8 + 2 * t;
        *(float2*)&Ob[(size_t)row0 * HID + col]       = make_float2(o[nb][0] * inv0, o[nb][1] * inv0);
        *(float2*)&Ob[(size_t)(row0 + 8) * HID + col] = make_float2(o[nb][2] * inv1, o[nb][3] * inv1);
    }
}

// ---------------------------------------------------------------------------
extern "C" void kernel_launch(void* const* d_in, const int* in_sizes, int n_in,
                              void* d_out, int out_size) {
    const float* hs = (const float*)d_in[0];
    const float* Wq = (const float*)d_in[1];
    const float* Wk = (const float*)d_in[2];
    const float* Wv = (const float*)d_in[3];
    const float* Wo = (const float*)d_in[4];
    const int* n_init  = (const int*)d_in[5];
    const int* n_local = (const int*)d_in[6];
    float* out = (float*)d_out;

    float *q, *k, *v, *attn;
    cudaGetSymbolAddress((void**)&q,    g_q);
    cudaGetSymbolAddress((void**)&k,    g_k);
    cudaGetSymbolAddress((void**)&v,    g_v);
    cudaGetSymbolAddress((void**)&attn, g_attn);
    float4 *pa_hs, *pa_at, *pb_wq, *pb_wk, *pb_wv, *pb_wo;
    cudaGetSymbolAddress((void**)&pa_hs, g_pa_hs);
    cudaGetSymbolAddress((void**)&pa_at, g_pa_at);
    cudaGetSymbolAddress((void**)&pb_wq, g_pb_wq);
    cudaGetSymbolAddress((void**)&pb_wk, g_pb_wk);
    cudaGetSymbolAddress((void**)&pb_wv, g_pb_wv);
    cudaGetSymbolAddress((void**)&pb_wo, g_pb_wo);

    static int attr_set = 0;
    if (!attr_set) {
        cudaFuncSetAttribute(attn_mma, cudaFuncAttributeMaxDynamicSharedMemorySize, ASMEM);
        cudaFuncSetAttribute(gemm_pk2, cudaFuncAttributeMaxDynamicSharedMemorySize, PK2_SMEM);
        attr_set = 1;
    }

    const int na_hs = (S_LEN / 128) * KS * 512;
    const int nb_wq = (HID / 128) * KS * 512;
    const int nb_wk = (KVDIM / 128) * KS * 512;

    pack_a<<<na_hs / 256, 256>>>(hs, pa_hs, na_hs);
    pack_b<<<nb_wq / 256, 256>>>(Wq, pb_wq, nb_wq);
    pack_b<<<nb_wk / 256, 256>>>(Wk, pb_wk, nb_wk);
    pack_b<<<nb_wk / 256, 256>>>(Wv, pb_wv, nb_wk);
    pack_b<<<nb_wq / 256, 256>>>(Wo, pb_wo, nb_wq);

    // Fused QKV projection: N tiles of 256 -> q:16, k:4, v:4
    gemm_pk2<<<dim3(24, S_LEN / 128), 256, PK2_SMEM>>>(
        pa_hs,
        pb_wq, 16, q, HID,
        pb_wk, 4,  k, KVDIM,
        pb_wv, 4,  v, KVDIM);

    attn_mma<<<dim3(S_LEN / ABQ, NH), 256, ASMEM>>>(q, k, v, attn, n_init, n_local);

    pack_a<<<na_hs / 256, 256>>>(attn, pa_at, na_hs);

    gemm_pk2<<<dim3(16, S_LEN / 128), 256, PK2_SMEM>>>(
        pa_at,
        pb_wo, 16, out, HID,
        pb_wo, 0,  out, HID,
        pb_wo, 0,  out, HID);
}